// round 1
// baseline (speedup 1.0000x reference)
#include <cuda_runtime.h>

#define D_MODEL 1024
#define N_HEADS 16
#define D_K     64
#define B_      2
#define S_      2048
#define M_TOT   (B_ * S_)          // 4096 rows for projection GEMMs
#define BH_     (B_ * N_HEADS)     // 32

// Scratch (allocation-free rule: __device__ globals).
// Q/K/V in [B,H,S,64] layout; O in [B,S,H,64] (= merged [4096,1024]).
__device__ float g_Q[(size_t)BH_ * S_ * D_K];
__device__ float g_K[(size_t)BH_ * S_ * D_K];
__device__ float g_V[(size_t)BH_ * S_ * D_K];
__device__ float g_O[(size_t)BH_ * S_ * D_K];

// ---------------------------------------------------------------------------
// Tiled SGEMM core: C[64x64] tile, K-tiles of 16, 256 threads, 4x4 microtile.
// A is [M,1024] row-major (inner dim contiguous), W is [N,1024] row-major
// (torch Linear weight: C[m,n] = sum_k A[m,k]*W[n,k] + bias[n]).
// Smem tiles stored transposed [k][m] / [k][n] with 68-float row stride
// (272 B = 16-aligned) so compute-side float4 reads are contiguous.
// ---------------------------------------------------------------------------

__device__ __forceinline__ void gemm_tile_compute(
    const float* __restrict__ A, const float* __restrict__ W,
    int m0, int n0, float acc[4][4], float As[16][68], float Bs[16][68],
    int tid, int tx, int ty)
{
    const int lrow = tid >> 2;          // 0..63
    const int lk   = (tid & 3) * 4;     // 0,4,8,12

    for (int k0 = 0; k0 < D_MODEL; k0 += 16) {
        float4 a = *(const float4*)&A[(size_t)(m0 + lrow) * D_MODEL + k0 + lk];
        float4 w = *(const float4*)&W[(size_t)(n0 + lrow) * D_MODEL + k0 + lk];
        As[lk + 0][lrow] = a.x; As[lk + 1][lrow] = a.y;
        As[lk + 2][lrow] = a.z; As[lk + 3][lrow] = a.w;
        Bs[lk + 0][lrow] = w.x; Bs[lk + 1][lrow] = w.y;
        Bs[lk + 2][lrow] = w.z; Bs[lk + 3][lrow] = w.w;
        __syncthreads();
        #pragma unroll
        for (int kk = 0; kk < 16; kk++) {
            float4 av = *(const float4*)&As[kk][ty * 4];
            float4 bv = *(const float4*)&Bs[kk][tx * 4];
            float am[4] = {av.x, av.y, av.z, av.w};
            float bm[4] = {bv.x, bv.y, bv.z, bv.w};
            #pragma unroll
            for (int i = 0; i < 4; i++)
                #pragma unroll
                for (int j = 0; j < 4; j++)
                    acc[i][j] += am[i] * bm[j];
        }
        __syncthreads();
    }
}

// QKV projection: grid (16, 64, 3). z selects Q/K/V. Output head-split.
__global__ __launch_bounds__(256)
void qkv_gemm(const float* __restrict__ x,
              const float* __restrict__ Wq, const float* __restrict__ bq,
              const float* __restrict__ Wk, const float* __restrict__ bk,
              const float* __restrict__ Wv, const float* __restrict__ bv)
{
    __shared__ float As[16][68];
    __shared__ float Bs[16][68];

    const float* W; const float* bias; float* out;
    if (blockIdx.z == 0)      { W = Wq; bias = bq; out = g_Q; }
    else if (blockIdx.z == 1) { W = Wk; bias = bk; out = g_K; }
    else                      { W = Wv; bias = bv; out = g_V; }

    const int tid = threadIdx.x;
    const int tx = tid & 15, ty = tid >> 4;
    const int m0 = blockIdx.y * 64;
    const int n0 = blockIdx.x * 64;   // gridDim.x = 16 -> n0 = head * 64

    float acc[4][4] = {};
    gemm_tile_compute(x, W, m0, n0, acc, As, Bs, tid, tx, ty);

    const int h = n0 >> 6;            // head index (tile aligned to head)
    const int dcol = tx * 4;          // col within head
    float4 bb4;
    bb4.x = bias[n0 + dcol + 0]; bb4.y = bias[n0 + dcol + 1];
    bb4.z = bias[n0 + dcol + 2]; bb4.w = bias[n0 + dcol + 3];
    #pragma unroll
    for (int i = 0; i < 4; i++) {
        int r = m0 + ty * 4 + i;      // global row in [0,4096)
        int b = r >> 11;              // /2048
        int s = r & (S_ - 1);
        float4 res;
        res.x = acc[i][0] + bb4.x; res.y = acc[i][1] + bb4.y;
        res.z = acc[i][2] + bb4.z; res.w = acc[i][3] + bb4.w;
        *(float4*)&out[(((size_t)b * N_HEADS + h) * S_ + s) * D_K + dcol] = res;
    }
}

// Output projection: grid (16, 64). Reads g_O as [4096,1024], writes d_out.
__global__ __launch_bounds__(256)
void out_gemm(const float* __restrict__ Wo, const float* __restrict__ bo,
              float* __restrict__ out)
{
    __shared__ float As[16][68];
    __shared__ float Bs[16][68];

    const int tid = threadIdx.x;
    const int tx = tid & 15, ty = tid >> 4;
    const int m0 = blockIdx.y * 64;
    const int n0 = blockIdx.x * 64;

    float acc[4][4] = {};
    gemm_tile_compute(g_O, Wo, m0, n0, acc, As, Bs, tid, tx, ty);

    const int ncol = n0 + tx * 4;
    float4 bb4;
    bb4.x = bo[ncol + 0]; bb4.y = bo[ncol + 1];
    bb4.z = bo[ncol + 2]; bb4.w = bo[ncol + 3];
    #pragma unroll
    for (int i = 0; i < 4; i++) {
        int r = m0 + ty * 4 + i;
        float4 res;
        res.x = acc[i][0] + bb4.x; res.y = acc[i][1] + bb4.y;
        res.z = acc[i][2] + bb4.z; res.w = acc[i][3] + bb4.w;
        *(float4*)&out[(size_t)r * D_MODEL + ncol] = res;
    }
}

// ---------------------------------------------------------------------------
// Fused attention (flash-style, fp32).
// Grid: (S/64, BH) = (32, 32). 256 threads. One 64-row Q tile per CTA.
// Smem (dynamic): Qs/Ks/Vs/Ps, each [64][68] floats (68 = 17*4 -> 272 B row
// stride, odd multiple of 16 B => conflict-free float4 column access).
// Per thread: q rows = ty*4+i, k cols (or d cols) = tx*4+j. Row-stat reduce
// across tx = shfl.bfly over 16-lane halves (warp = {ty, ty+1} x tx).
// ---------------------------------------------------------------------------
#define TSTRIDE 68
#define ATTN_SMEM (4 * 64 * TSTRIDE * (int)sizeof(float))  // 69632 B

__global__ __launch_bounds__(256)
void attn_kernel()
{
    extern __shared__ float sm[];
    float* Qs = sm;
    float* Ks = Qs + 64 * TSTRIDE;
    float* Vs = Ks + 64 * TSTRIDE;
    float* Ps = Vs + 64 * TSTRIDE;

    const int tid = threadIdx.x;
    const int tx = tid & 15, ty = tid >> 4;
    const int q0 = blockIdx.x * 64;
    const int bh = blockIdx.y;

    const float* Qg = g_Q + ((size_t)bh * S_ + q0) * D_K;
    const float* Kg = g_K + (size_t)bh * S_ * D_K;
    const float* Vg = g_V + (size_t)bh * S_ * D_K;

    const int lrow = tid >> 2;        // 0..63
    const int lc   = (tid & 3) * 4;   // 0,4,8,12

    // Load Q tile
    #pragma unroll
    for (int c = 0; c < 64; c += 16)
        *(float4*)&Qs[lrow * TSTRIDE + lc + c] =
            *(const float4*)&Qg[lrow * D_K + lc + c];

    float m_r[4], l_r[4], o_r[4][4];
    #pragma unroll
    for (int i = 0; i < 4; i++) {
        m_r[i] = -1e30f; l_r[i] = 0.f;
        #pragma unroll
        for (int j = 0; j < 4; j++) o_r[i][j] = 0.f;
    }

    for (int kt = 0; kt < S_; kt += 64) {
        __syncthreads();   // previous PV reads of Ks/Vs/Ps are done
        #pragma unroll
        for (int c = 0; c < 64; c += 16) {
            *(float4*)&Ks[lrow * TSTRIDE + lc + c] =
                *(const float4*)&Kg[(size_t)(kt + lrow) * D_K + lc + c];
            *(float4*)&Vs[lrow * TSTRIDE + lc + c] =
                *(const float4*)&Vg[(size_t)(kt + lrow) * D_K + lc + c];
        }
        __syncthreads();

        // S = Q K^T (4x4 per thread)
        float s_acc[4][4] = {};
        #pragma unroll
        for (int dd = 0; dd < 64; dd += 4) {
            float4 qv[4], kv[4];
            #pragma unroll
            for (int i = 0; i < 4; i++)
                qv[i] = *(const float4*)&Qs[(ty * 4 + i) * TSTRIDE + dd];
            #pragma unroll
            for (int j = 0; j < 4; j++)
                kv[j] = *(const float4*)&Ks[(tx * 4 + j) * TSTRIDE + dd];
            #pragma unroll
            for (int i = 0; i < 4; i++)
                #pragma unroll
                for (int j = 0; j < 4; j++)
                    s_acc[i][j] += qv[i].x * kv[j].x + qv[i].y * kv[j].y +
                                   qv[i].z * kv[j].z + qv[i].w * kv[j].w;
        }

        // Online softmax per q row
        #pragma unroll
        for (int i = 0; i < 4; i++) {
            #pragma unroll
            for (int j = 0; j < 4; j++) s_acc[i][j] *= 0.125f;  // 1/sqrt(64)
            float mx = fmaxf(fmaxf(s_acc[i][0], s_acc[i][1]),
                             fmaxf(s_acc[i][2], s_acc[i][3]));
            #pragma unroll
            for (int off = 1; off < 16; off <<= 1)
                mx = fmaxf(mx, __shfl_xor_sync(0xffffffffu, mx, off));
            float mnew = fmaxf(m_r[i], mx);
            float corr = __expf(m_r[i] - mnew);
            m_r[i] = mnew;
            float rs = 0.f;
            #pragma unroll
            for (int j = 0; j < 4; j++) {
                float p = __expf(s_acc[i][j] - mnew);
                s_acc[i][j] = p; rs += p;
            }
            #pragma unroll
            for (int off = 1; off < 16; off <<= 1)
                rs += __shfl_xor_sync(0xffffffffu, rs, off);
            l_r[i] = l_r[i] * corr + rs;
            #pragma unroll
            for (int j = 0; j < 4; j++) o_r[i][j] *= corr;
            float4 pw;
            pw.x = s_acc[i][0]; pw.y = s_acc[i][1];
            pw.z = s_acc[i][2]; pw.w = s_acc[i][3];
            *(float4*)&Ps[(ty * 4 + i) * TSTRIDE + tx * 4] = pw;
        }
        __syncthreads();

        // O += P V
        #pragma unroll
        for (int k = 0; k < 64; k += 4) {
            float4 pv[4], vv[4];
            #pragma unroll
            for (int i = 0; i < 4; i++)
                pv[i] = *(const float4*)&Ps[(ty * 4 + i) * TSTRIDE + k];
            #pragma unroll
            for (int kk = 0; kk < 4; kk++)
                vv[kk] = *(const float4*)&Vs[(k + kk) * TSTRIDE + tx * 4];
            #pragma unroll
            for (int i = 0; i < 4; i++) {
                o_r[i][0] += pv[i].x * vv[0].x + pv[i].y * vv[1].x +
                             pv[i].z * vv[2].x + pv[i].w * vv[3].x;
                o_r[i][1] += pv[i].x * vv[0].y + pv[i].y * vv[1].y +
                             pv[i].z * vv[2].y + pv[i].w * vv[3].y;
                o_r[i][2] += pv[i].x * vv[0].z + pv[i].y * vv[1].z +
                             pv[i].z * vv[2].z + pv[i].w * vv[3].z;
                o_r[i][3] += pv[i].x * vv[0].w + pv[i].y * vv[1].w +
                             pv[i].z * vv[2].w + pv[i].w * vv[3].w;
            }
        }
    }

    // Epilogue: normalize and write [B,S,H,64]
    const int b = bh >> 4, h = bh & 15;
    #pragma unroll
    for (int i = 0; i < 4; i++) {
        int q = q0 + ty * 4 + i;
        float inv = 1.0f / l_r[i];
        float4 res;
        res.x = o_r[i][0] * inv; res.y = o_r[i][1] * inv;
        res.z = o_r[i][2] * inv; res.w = o_r[i][3] * inv;
        *(float4*)&g_O[(((size_t)b * S_ + q) * N_HEADS + h) * D_K + tx * 4] = res;
    }
}

// ---------------------------------------------------------------------------
extern "C" void kernel_launch(void* const* d_in, const int* in_sizes, int n_in,
                              void* d_out, int out_size)
{
    const float* x  = (const float*)d_in[0];
    const float* Wq = (const float*)d_in[1];
    const float* bq = (const float*)d_in[2];
    const float* Wk = (const float*)d_in[3];
    const float* bk = (const float*)d_in[4];
    const float* Wv = (const float*)d_in[5];
    const float* bv = (const float*)d_in[6];
    const float* Wo = (const float*)d_in[7];
    const float* bo = (const float*)d_in[8];
    float* out = (float*)d_out;

    cudaFuncSetAttribute(attn_kernel,
                         cudaFuncAttributeMaxDynamicSharedMemorySize, ATTN_SMEM);

    dim3 gq(D_MODEL / 64, M_TOT / 64, 3);
    qkv_gemm<<<gq, 256>>>(x, Wq, bq, Wk, bk, Wv, bv);

    dim3 ga(S_ / 64, BH_);
    attn_kernel<<<ga, 256, ATTN_SMEM>>>();

    dim3 go(D_MODEL / 64, M_TOT / 64);
    out_gemm<<<go, 256>>>(Wo, bo, out);
}

// round 5
// speedup vs baseline: 2.2551x; 2.2551x over previous
#include <cuda_runtime.h>
#include <cuda_fp16.h>
#include <cstdint>

#define D_MODEL 1024
#define N_HEADS 16
#define D_K     64
#define B_      2
#define S_      2048
#define M_TOT   (B_ * S_)
#define BH_     (B_ * N_HEADS)

// ---------------------------------------------------------------------------
// Scratch (allocation-free): fp16 hi/lo operand arrays.
// ---------------------------------------------------------------------------
__device__ __half g_xh[(size_t)M_TOT * D_MODEL], g_xl[(size_t)M_TOT * D_MODEL];
__device__ __half g_Wh[4][(size_t)D_MODEL * D_MODEL];
__device__ __half g_Wl[4][(size_t)D_MODEL * D_MODEL];
// Q/K/V: [B,H,S,64]; O: [B,S,H,64]
__device__ __half g_Qh[(size_t)BH_ * S_ * D_K], g_Ql[(size_t)BH_ * S_ * D_K];
__device__ __half g_Kh[(size_t)BH_ * S_ * D_K], g_Kl[(size_t)BH_ * S_ * D_K];
__device__ __half g_Vh[(size_t)BH_ * S_ * D_K], g_Vl[(size_t)BH_ * S_ * D_K];
__device__ __half g_Oh[(size_t)BH_ * S_ * D_K], g_Ol[(size_t)BH_ * S_ * D_K];

__device__ __forceinline__ uint32_t smem_u32(const void* p) {
    uint32_t a;
    asm("{ .reg .u64 t; cvta.to.shared.u64 t, %1; cvt.u32.u64 %0, t; }"
        : "=r"(a) : "l"(p));
    return a;
}

// m16n8k16 fp16 mma, fp32 accumulate
#define MMA16(d, a, b0, b1)                                                  \
    asm volatile(                                                            \
        "mma.sync.aligned.m16n8k16.row.col.f32.f16.f16.f32 "                 \
        "{%0,%1,%2,%3}, {%4,%5,%6,%7}, {%8,%9}, {%0,%1,%2,%3};"              \
        : "+f"((d)[0]), "+f"((d)[1]), "+f"((d)[2]), "+f"((d)[3])             \
        : "r"((a)[0]), "r"((a)[1]), "r"((a)[2]), "r"((a)[3]),                \
          "r"(b0), "r"(b1))

#define CPA16(saddr, gptr)                                                   \
    asm volatile("cp.async.ca.shared.global [%0], [%1], 16;"                 \
                 :: "r"(saddr), "l"(gptr))
#define CPA_COMMIT() asm volatile("cp.async.commit_group;" ::: "memory")
#define CPA_WAIT0()  asm volatile("cp.async.wait_group 0;" ::: "memory")

// ---------------------------------------------------------------------------
// Split fp32 -> fp16 hi/lo. sel: 0=x, 1..4=Wq,Wk,Wv,Wo.
// ---------------------------------------------------------------------------
__global__ void __launch_bounds__(256) split_k(const float4* __restrict__ src, int sel)
{
    __half2 *hi, *lo;
    if (sel == 0) { hi = (__half2*)g_xh;        lo = (__half2*)g_xl; }
    else          { hi = (__half2*)g_Wh[sel-1]; lo = (__half2*)g_Wl[sel-1]; }
    const int i = blockIdx.x * 256 + threadIdx.x;
    float4 v = src[i];
    __half2 h0 = __floats2half2_rn(v.x, v.y);
    __half2 h1 = __floats2half2_rn(v.z, v.w);
    float2 f0 = __half22float2(h0), f1 = __half22float2(h1);
    hi[i * 2]     = h0;
    hi[i * 2 + 1] = h1;
    lo[i * 2]     = __floats2half2_rn(v.x - f0.x, v.y - f0.y);
    lo[i * 2 + 1] = __floats2half2_rn(v.z - f1.x, v.w - f1.y);
}

// ---------------------------------------------------------------------------
// fp16 3-term GEMM: C[128x128] = A[128,1024] @ W[128,1024]^T + bias.
// BK=16 halves, double-buffered cp.async. Smem row stride 12 half2
// (g*12 mod 32 covers all banks with tig lanes -> conflict-free).
// Warps 2(m) x 4(n), warp tile 64x32, m16n8k16.
// ---------------------------------------------------------------------------
#define GSTR  12                 // half2 per row
#define GTILE (128 * GSTR)       // half2 per array tile
#define GBUF  (4 * GTILE)        // Ah,Al,Bh,Bl per buffer
#define GEMM_SMEM (2 * GBUF * 4) // 49152 B

__global__ void __launch_bounds__(256, 2) gemm_f16(
    const float* __restrict__ bias, float* __restrict__ outp,
    int asel, int target)
{
    extern __shared__ uint32_t smv[];   // half2 units
    const int tid  = threadIdx.x;
    const int wid  = tid >> 5, lane = tid & 31;
    const int g    = lane >> 2, tig = lane & 3;
    const int wm   = (wid >> 2) * 64;
    const int wn   = (wid & 3) * 32;
    const int m0 = blockIdx.y * 128, n0 = blockIdx.x * 128;

    const __half* Ah = asel ? g_Oh : g_xh;
    const __half* Al = asel ? g_Ol : g_xl;
    const __half* Wh = g_Wh[target];
    const __half* Wl = g_Wl[target];
    __half *oh = nullptr, *ol = nullptr;
    if (target == 0)      { oh = g_Qh; ol = g_Ql; }
    else if (target == 1) { oh = g_Kh; ol = g_Kl; }
    else if (target == 2) { oh = g_Vh; ol = g_Vl; }
    const bool hs = (target < 3);

    // cp.async mapping: arr 0..3 = Ah,Al,Bh,Bl; t = row slot (rows t, t+64)
    const int arr = tid >> 6, t = tid & 63;
    const __half* srcs[4] = {Ah, Al, Wh, Wl};
    const int rb = (arr < 2) ? m0 : n0;
    const __half* sp = srcs[arr] + (size_t)(rb + t) * D_MODEL;
    const uint32_t sdst = smem_u32(smv) + (uint32_t)(arr * GTILE + t * GSTR) * 4;

    float acc[4][4][4];
    #pragma unroll
    for (int i = 0; i < 4; i++)
        #pragma unroll
        for (int j = 0; j < 4; j++)
            acc[i][j][0] = acc[i][j][1] = acc[i][j][2] = acc[i][j][3] = 0.f;

    // prologue: chunk 0 -> buf 0
    #pragma unroll
    for (int r = 0; r < 128; r += 64)
        #pragma unroll
        for (int s2 = 0; s2 < 2; s2++)
            CPA16(sdst + r * GSTR * 4 + s2 * 16, sp + (size_t)r * D_MODEL + s2 * 8);
    CPA_COMMIT();

    for (int c = 0; c < 64; c++) {
        const int buf = c & 1;
        CPA_WAIT0();
        __syncthreads();
        if (c + 1 < 64) {
            const uint32_t bo = (buf ^ 1) * GBUF * 4;
            const __half* s0 = sp + (size_t)(c + 1) * 16;
            #pragma unroll
            for (int r = 0; r < 128; r += 64)
                #pragma unroll
                for (int s2 = 0; s2 < 2; s2++)
                    CPA16(sdst + bo + r * GSTR * 4 + s2 * 16,
                          s0 + (size_t)r * D_MODEL + s2 * 8);
            CPA_COMMIT();
        }
        const uint32_t* S = smv + buf * GBUF;

        uint32_t bh[4][2], bl[4][2];
        #pragma unroll
        for (int nb = 0; nb < 4; nb++) {
            const int base = (wn + nb * 8 + g) * GSTR + tig;
            bh[nb][0] = S[2 * GTILE + base]; bh[nb][1] = S[2 * GTILE + base + 4];
            bl[nb][0] = S[3 * GTILE + base]; bl[nb][1] = S[3 * GTILE + base + 4];
        }
        #pragma unroll
        for (int mb = 0; mb < 4; mb++) {
            const int base = (wm + mb * 16 + g) * GSTR + tig;
            uint32_t ah[4] = {S[base], S[base + 8 * GSTR],
                              S[base + 4], S[base + 8 * GSTR + 4]};
            uint32_t al[4] = {S[GTILE + base], S[GTILE + base + 8 * GSTR],
                              S[GTILE + base + 4], S[GTILE + base + 8 * GSTR + 4]};
            #pragma unroll
            for (int nb = 0; nb < 4; nb++) {
                MMA16(acc[mb][nb], ah, bh[nb][0], bh[nb][1]);
                MMA16(acc[mb][nb], ah, bl[nb][0], bl[nb][1]);
                MMA16(acc[mb][nb], al, bh[nb][0], bh[nb][1]);
            }
        }
    }

    // epilogue
    #pragma unroll
    for (int nb = 0; nb < 4; nb++) {
        const int col = n0 + wn + nb * 8 + 2 * tig;
        const float b0 = bias[col], b1 = bias[col + 1];
        #pragma unroll
        for (int mb = 0; mb < 4; mb++) {
            const int row0 = m0 + wm + mb * 16 + g;
            #pragma unroll
            for (int hf = 0; hf < 2; hf++) {
                const int row = row0 + hf * 8;
                const float v0 = acc[mb][nb][hf * 2]     + b0;
                const float v1 = acc[mb][nb][hf * 2 + 1] + b1;
                if (hs) {
                    const int h = col >> 6, d0 = col & 63;
                    const int bb = row >> 11, ss = row & (S_ - 1);
                    const size_t idx =
                        (((size_t)bb * N_HEADS + h) * S_ + ss) * D_K + d0;
                    __half2 hi2 = __floats2half2_rn(v0, v1);
                    float2 hf2 = __half22float2(hi2);
                    *(__half2*)&oh[idx] = hi2;
                    *(__half2*)&ol[idx] = __floats2half2_rn(v0 - hf2.x, v1 - hf2.y);
                } else {
                    *(float2*)&outp[(size_t)row * D_MODEL + col] =
                        make_float2(v0, v1);
                }
            }
        }
    }
}

// ---------------------------------------------------------------------------
// Fused flash attention, fp16 3-term mma.
// CTA: 128 q x 128 kt, 8 warps (2m x 4n). Smem strides 36/68 half2 -> CF.
// ---------------------------------------------------------------------------
#define OQH  0
#define OQL  4608
#define OKH  9216
#define OKL  13824
#define OVTH 18432
#define OVTL 22784
#define OPH  27136
#define OPL  35840
#define ORED 44544                       // float index (== word index)
#define ATT_SMEM ((44544 + 1024) * 4)    // 182272 B

__global__ void __launch_bounds__(256, 1) attn_f16()
{
    extern __shared__ uint32_t smv[];
    float* smf = (float*)smv;
    const int tid  = threadIdx.x;
    const int wid  = tid >> 5, lane = tid & 31;
    const int g    = lane >> 2, tig = lane & 3;
    const int wm   = (wid >> 2) * 64;
    const int wn   = (wid & 3) * 32;
    const int wnv  = (wid & 3) * 16;
    const int q0 = blockIdx.x * 128;
    const int bh = blockIdx.y;

    const size_t hb = (size_t)bh * S_ * D_K;

    // Q tile: thread handles full 64-half row `row` of array `ar`.
    {
        const int row = tid >> 1, ar = tid & 1;
        const __half* src = (ar ? g_Ql : g_Qh) + hb + (size_t)(q0 + row) * D_K;
        uint32_t* dst = smv + (ar ? OQL : OQH) + row * 36;
        #pragma unroll
        for (int s2 = 0; s2 < 8; s2++)
            *(uint4*)(dst + s2 * 4) = *(const uint4*)(src + s2 * 8);
    }

    float m_r[8], l_r[8], o_acc[4][2][4];
    #pragma unroll
    for (int s = 0; s < 8; s++) { m_r[s] = -1e30f; l_r[s] = 0.f; }
    #pragma unroll
    for (int mb = 0; mb < 4; mb++)
        #pragma unroll
        for (int nb = 0; nb < 2; nb++)
            o_acc[mb][nb][0] = o_acc[mb][nb][1] =
            o_acc[mb][nb][2] = o_acc[mb][nb][3] = 0.f;

    for (int kt = 0; kt < S_; kt += 128) {
        __syncthreads();
        // K tile: full row copy, same scheme as Q.
        {
            const int row = tid >> 1, ar = tid & 1;
            const __half* src = (ar ? g_Kl : g_Kh) + hb + (size_t)(kt + row) * D_K;
            uint32_t* dst = smv + (ar ? OKL : OKH) + row * 36;
            #pragma unroll
            for (int s2 = 0; s2 < 8; s2++)
                *(uint4*)(dst + s2 * 4) = *(const uint4*)(src + s2 * 8);
        }
        // V transposed: tid<128; ar = tid>>6, kt-pair p = tid&63 handles
        // rows 2p, 2p+1 across all 64 d values.
        if (tid < 128) {
            const int ar = tid >> 6, p = tid & 63;
            const __half* v0 = (ar ? g_Vl : g_Vh) + hb + (size_t)(kt + 2 * p) * D_K;
            const __half* v1 = v0 + D_K;
            uint32_t* vt = smv + (ar ? OVTL : OVTH);
            #pragma unroll
            for (int c = 0; c < 8; c++) {
                uint4 r0 = *(const uint4*)(v0 + c * 8);
                uint4 r1 = *(const uint4*)(v1 + c * 8);
                const __half2* pa = (const __half2*)&r0;
                const __half2* pb = (const __half2*)&r1;
                #pragma unroll
                for (int i = 0; i < 4; i++) {
                    const int d = c * 8 + 2 * i;
                    *(__half2*)&vt[(d + 0) * 68 + p] = __lows2half2(pa[i], pb[i]);
                    *(__half2*)&vt[(d + 1) * 68 + p] = __highs2half2(pa[i], pb[i]);
                }
            }
        }
        __syncthreads();

        // ---- S = Q K^T, 3-term ----
        float s_acc[4][4][4];
        #pragma unroll
        for (int mb = 0; mb < 4; mb++)
            #pragma unroll
            for (int nb = 0; nb < 4; nb++)
                s_acc[mb][nb][0] = s_acc[mb][nb][1] =
                s_acc[mb][nb][2] = s_acc[mb][nb][3] = 0.f;

        #pragma unroll
        for (int st = 0; st < 4; st++) {          // d = 16*st
            uint32_t bhf[4][2], blf[4][2];
            #pragma unroll
            for (int nb = 0; nb < 4; nb++) {
                const int base = (wn + nb * 8 + g) * 36 + st * 8 + tig;
                bhf[nb][0] = smv[OKH + base]; bhf[nb][1] = smv[OKH + base + 4];
                blf[nb][0] = smv[OKL + base]; blf[nb][1] = smv[OKL + base + 4];
            }
            #pragma unroll
            for (int mb = 0; mb < 4; mb++) {
                const int base = (wm + mb * 16 + g) * 36 + st * 8 + tig;
                uint32_t ah[4] = {smv[OQH + base], smv[OQH + base + 8 * 36],
                                  smv[OQH + base + 4], smv[OQH + base + 8 * 36 + 4]};
                uint32_t al[4] = {smv[OQL + base], smv[OQL + base + 8 * 36],
                                  smv[OQL + base + 4], smv[OQL + base + 8 * 36 + 4]};
                #pragma unroll
                for (int nb = 0; nb < 4; nb++) {
                    MMA16(s_acc[mb][nb], ah, bhf[nb][0], bhf[nb][1]);
                    MMA16(s_acc[mb][nb], ah, blf[nb][0], blf[nb][1]);
                    MMA16(s_acc[mb][nb], al, bhf[nb][0], bhf[nb][1]);
                }
            }
        }

        // ---- online softmax (rows split across 4 n-warps) ----
        #pragma unroll
        for (int s = 0; s < 8; s++) {
            const int mb = s >> 1, ro = (s & 1) * 2;
            float v = fmaxf(s_acc[mb][0][ro], s_acc[mb][0][ro + 1]);
            #pragma unroll
            for (int nb = 1; nb < 4; nb++)
                v = fmaxf(v, fmaxf(s_acc[mb][nb][ro], s_acc[mb][nb][ro + 1]));
            v = fmaxf(v, __shfl_xor_sync(0xffffffffu, v, 1));
            v = fmaxf(v, __shfl_xor_sync(0xffffffffu, v, 2));
            if (tig == 0) {
                const int row = wm + mb * 16 + g + (s & 1) * 8;
                smf[ORED + row * 4 + (wid & 3)] = v;
            }
        }
        __syncthreads();

        float corr[8], mnew[8];
        #pragma unroll
        for (int s = 0; s < 8; s++) {
            const int row = wm + (s >> 1) * 16 + g + (s & 1) * 8;
            float mx = fmaxf(fmaxf(smf[ORED + row * 4], smf[ORED + row * 4 + 1]),
                             fmaxf(smf[ORED + row * 4 + 2], smf[ORED + row * 4 + 3]));
            mx *= 0.125f;
            mnew[s] = fmaxf(m_r[s], mx);
            corr[s] = __expf(m_r[s] - mnew[s]);
            m_r[s]  = mnew[s];
        }

        #pragma unroll
        for (int s = 0; s < 8; s++) {
            const int mb = s >> 1, ro = (s & 1) * 2;
            float sum = 0.f;
            #pragma unroll
            for (int nb = 0; nb < 4; nb++) {
                float p0 = __expf(s_acc[mb][nb][ro]     * 0.125f - mnew[s]);
                float p1 = __expf(s_acc[mb][nb][ro + 1] * 0.125f - mnew[s]);
                s_acc[mb][nb][ro] = p0; s_acc[mb][nb][ro + 1] = p1;
                sum += p0 + p1;
            }
            sum += __shfl_xor_sync(0xffffffffu, sum, 1);
            sum += __shfl_xor_sync(0xffffffffu, sum, 2);
            if (tig == 0) {
                const int row = wm + mb * 16 + g + (s & 1) * 8;
                smf[ORED + 512 + row * 4 + (wid & 3)] = sum;
            }
        }
        __syncthreads();

        #pragma unroll
        for (int s = 0; s < 8; s++) {
            const int row = wm + (s >> 1) * 16 + g + (s & 1) * 8;
            const float* rs = &smf[ORED + 512 + row * 4];
            l_r[s] = l_r[s] * corr[s] + (rs[0] + rs[1] + rs[2] + rs[3]);
        }
        #pragma unroll
        for (int mb = 0; mb < 4; mb++)
            #pragma unroll
            for (int nb = 0; nb < 2; nb++) {
                o_acc[mb][nb][0] *= corr[mb * 2];
                o_acc[mb][nb][1] *= corr[mb * 2];
                o_acc[mb][nb][2] *= corr[mb * 2 + 1];
                o_acc[mb][nb][3] *= corr[mb * 2 + 1];
            }

        // P split hi/lo -> smem [q][kt], stride 68 half2
        #pragma unroll
        for (int mb = 0; mb < 4; mb++) {
            const int r0 = wm + mb * 16 + g;
            #pragma unroll
            for (int nb = 0; nb < 4; nb++) {
                const int cp = (wn >> 1) + nb * 4 + tig;
                #pragma unroll
                for (int hf = 0; hf < 2; hf++) {
                    const int r = r0 + hf * 8;
                    const float p0 = s_acc[mb][nb][hf * 2];
                    const float p1 = s_acc[mb][nb][hf * 2 + 1];
                    __half2 hi2 = __floats2half2_rn(p0, p1);
                    float2 hf2 = __half22float2(hi2);
                    *(__half2*)&smv[OPH + r * 68 + cp] = hi2;
                    *(__half2*)&smv[OPL + r * 68 + cp] =
                        __floats2half2_rn(p0 - hf2.x, p1 - hf2.y);
                }
            }
        }
        __syncthreads();

        // ---- O += P V, 3-term ----
        #pragma unroll
        for (int k = 0; k < 8; k++) {             // kt chunk = 16*k
            uint32_t bhf[2][2], blf[2][2];
            #pragma unroll
            for (int nb = 0; nb < 2; nb++) {
                const int base = (wnv + nb * 8 + g) * 68 + k * 8 + tig;
                bhf[nb][0] = smv[OVTH + base]; bhf[nb][1] = smv[OVTH + base + 4];
                blf[nb][0] = smv[OVTL + base]; blf[nb][1] = smv[OVTL + base + 4];
            }
            #pragma unroll
            for (int mb = 0; mb < 4; mb++) {
                const int base = (wm + mb * 16 + g) * 68 + k * 8 + tig;
                uint32_t ah[4] = {smv[OPH + base], smv[OPH + base + 8 * 68],
                                  smv[OPH + base + 4], smv[OPH + base + 8 * 68 + 4]};
                uint32_t al[4] = {smv[OPL + base], smv[OPL + base + 8 * 68],
                                  smv[OPL + base + 4], smv[OPL + base + 8 * 68 + 4]};
                #pragma unroll
                for (int nb = 0; nb < 2; nb++) {
                    MMA16(o_acc[mb][nb], ah, bhf[nb][0], bhf[nb][1]);
                    MMA16(o_acc[mb][nb], ah, blf[nb][0], blf[nb][1]);
                    MMA16(o_acc[mb][nb], al, bhf[nb][0], bhf[nb][1]);
                }
            }
        }
    }

    // epilogue: normalize, split hi/lo, write [B,S,H,64]
    const int b = bh >> 4, h = bh & 15;
    #pragma unroll
    for (int mb = 0; mb < 4; mb++) {
        #pragma unroll
        for (int hf = 0; hf < 2; hf++) {
            const float inv = 1.0f / l_r[mb * 2 + hf];
            const int q = q0 + wm + mb * 16 + g + hf * 8;
            #pragma unroll
            for (int nb = 0; nb < 2; nb++) {
                const int col = wnv + nb * 8 + 2 * tig;
                const float v0 = o_acc[mb][nb][hf * 2]     * inv;
                const float v1 = o_acc[mb][nb][hf * 2 + 1] * inv;
                const size_t idx =
                    (((size_t)b * S_ + q) * N_HEADS + h) * D_K + col;
                __half2 hi2 = __floats2half2_rn(v0, v1);
                float2 hf2 = __half22float2(hi2);
                *(__half2*)&g_Oh[idx] = hi2;
                *(__half2*)&g_Ol[idx] = __floats2half2_rn(v0 - hf2.x, v1 - hf2.y);
            }
        }
    }
}

// ---------------------------------------------------------------------------
extern "C" void kernel_launch(void* const* d_in, const int* in_sizes, int n_in,
                              void* d_out, int out_size)
{
    const float* x  = (const float*)d_in[0];
    const float* Wq = (const float*)d_in[1];
    const float* bq = (const float*)d_in[2];
    const float* Wk = (const float*)d_in[3];
    const float* bk = (const float*)d_in[4];
    const float* Wv = (const float*)d_in[5];
    const float* bv = (const float*)d_in[6];
    const float* Wo = (const float*)d_in[7];
    const float* bo = (const float*)d_in[8];
    float* out = (float*)d_out;

    cudaFuncSetAttribute(gemm_f16, cudaFuncAttributeMaxDynamicSharedMemorySize,
                         GEMM_SMEM);
    cudaFuncSetAttribute(attn_f16, cudaFuncAttributeMaxDynamicSharedMemorySize,
                         ATT_SMEM);

    split_k<<<M_TOT * D_MODEL / 1024, 256>>>((const float4*)x,  0);
    split_k<<<D_MODEL * D_MODEL / 1024, 256>>>((const float4*)Wq, 1);
    split_k<<<D_MODEL * D_MODEL / 1024, 256>>>((const float4*)Wk, 2);
    split_k<<<D_MODEL * D_MODEL / 1024, 256>>>((const float4*)Wv, 3);
    split_k<<<D_MODEL * D_MODEL / 1024, 256>>>((const float4*)Wo, 4);

    dim3 gg(D_MODEL / 128, M_TOT / 128);   // (8, 32)
    gemm_f16<<<gg, 256, GEMM_SMEM>>>(bq, nullptr, 0, 0);
    gemm_f16<<<gg, 256, GEMM_SMEM>>>(bk, nullptr, 0, 1);
    gemm_f16<<<gg, 256, GEMM_SMEM>>>(bv, nullptr, 0, 2);

    attn_f16<<<dim3(S_ / 128, BH_), 256, ATT_SMEM>>>();

    gemm_f16<<<gg, 256, GEMM_SMEM>>>(bo, out, 1, 3);
}

// round 7
// speedup vs baseline: 2.7733x; 1.2298x over previous
#include <cuda_runtime.h>
#include <cuda_fp16.h>
#include <cstdint>

#define D_MODEL 1024
#define N_HEADS 16
#define D_K     64
#define B_      2
#define S_      2048
#define M_TOT   (B_ * S_)
#define BH_     (B_ * N_HEADS)

// ---------------------------------------------------------------------------
// Scratch (allocation-free): fp16 hi/lo operand arrays.
// ---------------------------------------------------------------------------
__device__ __half g_xh[(size_t)M_TOT * D_MODEL], g_xl[(size_t)M_TOT * D_MODEL];
__device__ __half g_Wh[4][(size_t)D_MODEL * D_MODEL];
__device__ __half g_Wl[4][(size_t)D_MODEL * D_MODEL];
// Q/K/V: [B,H,S,64]; O: [B,S,H,64]
__device__ __half g_Qh[(size_t)BH_ * S_ * D_K], g_Ql[(size_t)BH_ * S_ * D_K];
__device__ __half g_Kh[(size_t)BH_ * S_ * D_K], g_Kl[(size_t)BH_ * S_ * D_K];
__device__ __half g_Vh[(size_t)BH_ * S_ * D_K], g_Vl[(size_t)BH_ * S_ * D_K];
__device__ __half g_Oh[(size_t)BH_ * S_ * D_K], g_Ol[(size_t)BH_ * S_ * D_K];

__device__ __forceinline__ uint32_t smem_u32(const void* p) {
    uint32_t a;
    asm("{ .reg .u64 t; cvta.to.shared.u64 t, %1; cvt.u32.u64 %0, t; }"
        : "=r"(a) : "l"(p));
    return a;
}

#define MMA16(d, a, b0, b1)                                                  \
    asm volatile(                                                            \
        "mma.sync.aligned.m16n8k16.row.col.f32.f16.f16.f32 "                 \
        "{%0,%1,%2,%3}, {%4,%5,%6,%7}, {%8,%9}, {%0,%1,%2,%3};"              \
        : "+f"((d)[0]), "+f"((d)[1]), "+f"((d)[2]), "+f"((d)[3])             \
        : "r"((a)[0]), "r"((a)[1]), "r"((a)[2]), "r"((a)[3]),                \
          "r"(b0), "r"(b1))

#define LDSM4(r0, r1, r2, r3, a)                                             \
    asm volatile("ldmatrix.sync.aligned.m8n8.x4.shared.b16 {%0,%1,%2,%3}, [%4];" \
        : "=r"(r0), "=r"(r1), "=r"(r2), "=r"(r3) : "r"(a))
#define LDSM4T(r0, r1, r2, r3, a)                                            \
    asm volatile("ldmatrix.sync.aligned.m8n8.x4.trans.shared.b16 {%0,%1,%2,%3}, [%4];" \
        : "=r"(r0), "=r"(r1), "=r"(r2), "=r"(r3) : "r"(a))

#define CPA16(saddr, gptr)                                                   \
    asm volatile("cp.async.ca.shared.global [%0], [%1], 16;"                 \
                 :: "r"(saddr), "l"(gptr))
#define CPA_COMMIT() asm volatile("cp.async.commit_group;" ::: "memory")
#define CPA_WAIT0()  asm volatile("cp.async.wait_group 0;" ::: "memory")

// ---------------------------------------------------------------------------
// Split fp32 -> fp16 hi/lo. sel: 0=x, 1..4=Wq,Wk,Wv,Wo.
// ---------------------------------------------------------------------------
__global__ void __launch_bounds__(256) split_k(const float4* __restrict__ src, int sel)
{
    __half2 *hi, *lo;
    if (sel == 0) { hi = (__half2*)g_xh;        lo = (__half2*)g_xl; }
    else          { hi = (__half2*)g_Wh[sel-1]; lo = (__half2*)g_Wl[sel-1]; }
    const int i = blockIdx.x * 256 + threadIdx.x;
    float4 v = src[i];
    __half2 h0 = __floats2half2_rn(v.x, v.y);
    __half2 h1 = __floats2half2_rn(v.z, v.w);
    float2 f0 = __half22float2(h0), f1 = __half22float2(h1);
    hi[i * 2]     = h0;
    hi[i * 2 + 1] = h1;
    lo[i * 2]     = __floats2half2_rn(v.x - f0.x, v.y - f0.y);
    lo[i * 2 + 1] = __floats2half2_rn(v.z - f1.x, v.w - f1.y);
}

// ---------------------------------------------------------------------------
// fp16 3-term GEMM, BK=32, ldmatrix fragments, cp.async double buffer.
// mode 0: fused QKV, grid (24, 32), target = bx>>3.
// mode 1: out-proj, grid (8, 32), A = g_O, writes fp32 out.
// Smem row stride 20 words (16 data + 4 pad).
// ---------------------------------------------------------------------------
#define GSTR  20                  // words per row
#define GTILE (128 * GSTR)        // words per array tile
#define GBUF  (4 * GTILE)         // Ah,Al,Bh,Bl
#define GEMM_SMEM (2 * GBUF * 4)  // 81920 B

__global__ void __launch_bounds__(256, 2) gemm_f16(
    const float* __restrict__ b0p, const float* __restrict__ b1p,
    const float* __restrict__ b2p, float* __restrict__ outp, int mode)
{
    extern __shared__ uint32_t smv[];
    const int tid = threadIdx.x;
    const int wid = tid >> 5, lane = tid & 31;
    const int g   = lane >> 2, tig = lane & 3;
    const int wm  = (wid >> 2) * 64;
    const int wn  = (wid & 3) * 32;
    const int bx = blockIdx.x;
    const int m0 = blockIdx.y * 128;
    const int target = mode ? 3 : (bx >> 3);
    const int n0 = (mode ? bx : (bx & 7)) * 128;

    const __half* Ah = mode ? g_Oh : g_xh;
    const __half* Al = mode ? g_Ol : g_xl;
    const __half* Wh = g_Wh[target];
    const __half* Wl = g_Wl[target];
    const float* bias = mode ? b0p
                             : (target == 0 ? b0p : target == 1 ? b1p : b2p);
    __half *oh = nullptr, *ol = nullptr;
    if (target == 0)      { oh = g_Qh; ol = g_Ql; }
    else if (target == 1) { oh = g_Kh; ol = g_Kl; }
    else if (target == 2) { oh = g_Vh; ol = g_Vl; }
    const bool hs = (mode == 0);

    // cp.async mapping: arr 0..3 = Ah,Al,Bh,Bl; rows t, t+64; 32 halves each.
    const int arr = tid >> 6, t = tid & 63;
    const __half* srcs[4] = {Ah, Al, Wh, Wl};
    const int rb = (arr < 2) ? m0 : n0;
    const __half* sp = srcs[arr] + (size_t)(rb + t) * D_MODEL;
    const uint32_t sbase = smem_u32(smv);
    const uint32_t sdst = sbase + (uint32_t)(arr * GTILE + t * GSTR) * 4;

    float acc[4][4][4];
    #pragma unroll
    for (int i = 0; i < 4; i++)
        #pragma unroll
        for (int j = 0; j < 4; j++)
            acc[i][j][0] = acc[i][j][1] = acc[i][j][2] = acc[i][j][3] = 0.f;

    // prologue: chunk 0 -> buf 0 (rows are 32 halves = 64 B here)
    #pragma unroll
    for (int r = 0; r < 2; r++)
        #pragma unroll
        for (int j = 0; j < 4; j++)
            CPA16(sdst + r * 64 * GSTR * 4 + j * 16,
                  sp + (size_t)r * 64 * D_MODEL + j * 8);
    CPA_COMMIT();

    // ldmatrix per-lane offsets (bytes)
    const uint32_t a_off = ((wm + (lane & 15)) * GSTR + ((lane >> 4) << 2)) * 4;
    const uint32_t b_off = ((wn + (lane & 7) + ((lane >> 4) << 3)) * GSTR
                            + (((lane >> 3) & 1) << 2)) * 4;

    for (int c = 0; c < 32; c++) {
        const int buf = c & 1;
        CPA_WAIT0();
        __syncthreads();
        if (c + 1 < 32) {
            const uint32_t bo = (buf ^ 1) * GBUF * 4;
            const __half* s0 = sp + (c + 1) * 32;
            #pragma unroll
            for (int r = 0; r < 2; r++)
                #pragma unroll
                for (int j = 0; j < 4; j++)
                    CPA16(sdst + bo + r * 64 * GSTR * 4 + j * 16,
                          s0 + (size_t)r * 64 * D_MODEL + j * 8);
            CPA_COMMIT();
        }
        const uint32_t Bb = sbase + buf * GBUF * 4;
        #pragma unroll
        for (int st = 0; st < 2; st++) {
            uint32_t bh[4][2], bl[4][2];
            #pragma unroll
            for (int p = 0; p < 2; p++) {
                uint32_t ad = Bb + 2 * GTILE * 4 + b_off
                              + (p * 16 * GSTR + st * 8) * 4;
                LDSM4(bh[2*p][0], bh[2*p][1], bh[2*p+1][0], bh[2*p+1][1], ad);
                LDSM4(bl[2*p][0], bl[2*p][1], bl[2*p+1][0], bl[2*p+1][1],
                      ad + GTILE * 4);
            }
            #pragma unroll
            for (int mb = 0; mb < 4; mb++) {
                uint32_t ah[4], al[4];
                const uint32_t ad = Bb + a_off + (mb * 16 * GSTR + st * 8) * 4;
                LDSM4(ah[0], ah[1], ah[2], ah[3], ad);
                LDSM4(al[0], al[1], al[2], al[3], ad + GTILE * 4);
                #pragma unroll
                for (int nb = 0; nb < 4; nb++) {
                    MMA16(acc[mb][nb], ah, bh[nb][0], bh[nb][1]);
                    MMA16(acc[mb][nb], ah, bl[nb][0], bl[nb][1]);
                    MMA16(acc[mb][nb], al, bh[nb][0], bh[nb][1]);
                }
            }
        }
    }

    // epilogue
    #pragma unroll
    for (int nb = 0; nb < 4; nb++) {
        const int col = n0 + wn + nb * 8 + 2 * tig;
        const float b0 = bias[col], b1 = bias[col + 1];
        #pragma unroll
        for (int mb = 0; mb < 4; mb++) {
            const int row0 = m0 + wm + mb * 16 + g;
            #pragma unroll
            for (int hf = 0; hf < 2; hf++) {
                const int row = row0 + hf * 8;
                const float v0 = acc[mb][nb][hf * 2]     + b0;
                const float v1 = acc[mb][nb][hf * 2 + 1] + b1;
                if (hs) {
                    const int h = col >> 6, d0 = col & 63;
                    const int bb = row >> 11, ss = row & (S_ - 1);
                    const size_t idx =
                        (((size_t)bb * N_HEADS + h) * S_ + ss) * D_K + d0;
                    __half2 hi2 = __floats2half2_rn(v0, v1);
                    float2 hf2 = __half22float2(hi2);
                    *(__half2*)&oh[idx] = hi2;
                    *(__half2*)&ol[idx] = __floats2half2_rn(v0 - hf2.x, v1 - hf2.y);
                } else {
                    *(float2*)&outp[(size_t)row * D_MODEL + col] =
                        make_float2(v0, v1);
                }
            }
        }
    }
}

// ---------------------------------------------------------------------------
// Fused flash attention: cp.async double-buffered K/V, ldmatrix fragments,
// 3-term S, 2-term PV (P hi only). 128 q x 128 kt tiles, 8 warps (2m x 4n).
// Strides (words): Q/K/V 36, P 68.
// ---------------------------------------------------------------------------
#define OQH  0
#define OQL  4608
#define OK0  9216          // + buf*9216 + arr*4608 + row*36
#define OV0  27648
#define OPH  46080         // stride 68
#define ORED 54784
#define ATT_SMEM (55808 * 4)   // 223232 B

__global__ void __launch_bounds__(256, 1) attn_f16()
{
    extern __shared__ uint32_t smv[];
    float* smf = (float*)smv;
    const int tid  = threadIdx.x;
    const int wid  = tid >> 5, lane = tid & 31;
    const int g    = lane >> 2, tig = lane & 3;
    const int wm   = (wid >> 2) * 64;
    const int wn   = (wid & 3) * 32;
    const int wnv  = (wid & 3) * 16;
    const int q0 = blockIdx.x * 128;
    const int bhid = blockIdx.y;
    const size_t hb = (size_t)bhid * S_ * D_K;
    const uint32_t sbase = smem_u32(smv);

    // Q tile load (hi+lo), one 64-half row per thread.
    {
        const int row = tid >> 1, ar = tid & 1;
        const __half* src = (ar ? g_Ql : g_Qh) + hb + (size_t)(q0 + row) * D_K;
        uint32_t* dst = smv + (ar ? OQL : OQH) + row * 36;
        #pragma unroll
        for (int s2 = 0; s2 < 8; s2++)
            *(uint4*)(dst + s2 * 4) = *(const uint4*)(src + s2 * 8);
    }

    // K/V cp.async tile loader: arr 0..3 = Kh,Kl,Vh,Vl; rows lrow, lrow+64.
    // Each row is 64 halves = 128 B = 8 x 16 B.
    const __half* kvsrc0[4] = {g_Kh + hb, g_Kl + hb, g_Vh + hb, g_Vl + hb};
    const int larr = tid >> 6, lrow = tid & 63;
    const __half* lsp = kvsrc0[larr] + (size_t)lrow * D_K;
    const uint32_t ldst = sbase +
        (uint32_t)((larr < 2 ? OK0 : OV0) + (larr & 1) * 4608 + lrow * 36) * 4;

    auto load_tile = [&](int tt, int buf) {
        const __half* s0 = lsp + (size_t)tt * 128 * D_K;
        const uint32_t d0 = ldst + buf * 9216 * 4;
        #pragma unroll
        for (int r = 0; r < 2; r++)
            #pragma unroll
            for (int j = 0; j < 8; j++)
                CPA16(d0 + r * 64 * 36 * 4 + j * 16,
                      s0 + (size_t)r * 64 * D_K + j * 8);
        CPA_COMMIT();
    };

    // ldmatrix per-lane offsets (bytes)
    const uint32_t qa_off = ((wm + (lane & 15)) * 36 + ((lane >> 4) << 2)) * 4;
    const uint32_t kb_off = ((wn + (lane & 7) + ((lane >> 4) << 3)) * 36
                             + (((lane >> 3) & 1) << 2)) * 4;
    const uint32_t pa_off = ((wm + (lane & 15)) * 68 + ((lane >> 4) << 2)) * 4;
    const uint32_t vb_off = (((lane & 7) + (((lane >> 3) & 1) << 3)) * 36
                             + (wnv >> 1) + ((lane >> 4) << 2)) * 4;

    float m_r[8], l_r[8], o_acc[4][2][4];
    #pragma unroll
    for (int s = 0; s < 8; s++) { m_r[s] = -1e30f; l_r[s] = 0.f; }
    #pragma unroll
    for (int mb = 0; mb < 4; mb++)
        #pragma unroll
        for (int nb = 0; nb < 2; nb++)
            o_acc[mb][nb][0] = o_acc[mb][nb][1] =
            o_acc[mb][nb][2] = o_acc[mb][nb][3] = 0.f;

    load_tile(0, 0);

    for (int t = 0; t < S_ / 128; t++) {
        const int buf = t & 1;
        CPA_WAIT0();
        __syncthreads();

        // ---- S = Q K^T, 3-term ----
        float s_acc[4][4][4];
        #pragma unroll
        for (int mb = 0; mb < 4; mb++)
            #pragma unroll
            for (int nb = 0; nb < 4; nb++)
                s_acc[mb][nb][0] = s_acc[mb][nb][1] =
                s_acc[mb][nb][2] = s_acc[mb][nb][3] = 0.f;

        const uint32_t kB = sbase + (OK0 + buf * 9216) * 4;
        #pragma unroll
        for (int st = 0; st < 4; st++) {
            uint32_t bh[4][2], bl[4][2];
            #pragma unroll
            for (int p = 0; p < 2; p++) {
                const uint32_t ad = kB + kb_off + (p * 16 * 36 + st * 8) * 4;
                LDSM4(bh[2*p][0], bh[2*p][1], bh[2*p+1][0], bh[2*p+1][1], ad);
                LDSM4(bl[2*p][0], bl[2*p][1], bl[2*p+1][0], bl[2*p+1][1],
                      ad + 4608 * 4);
            }
            #pragma unroll
            for (int mb = 0; mb < 4; mb++) {
                uint32_t ah[4], al[4];
                const uint32_t ad = sbase + qa_off + (mb * 16 * 36 + st * 8) * 4;
                LDSM4(ah[0], ah[1], ah[2], ah[3], ad);
                LDSM4(al[0], al[1], al[2], al[3], ad + OQL * 4);
                #pragma unroll
                for (int nb = 0; nb < 4; nb++) {
                    MMA16(s_acc[mb][nb], ah, bh[nb][0], bh[nb][1]);
                    MMA16(s_acc[mb][nb], ah, bl[nb][0], bl[nb][1]);
                    MMA16(s_acc[mb][nb], al, bh[nb][0], bh[nb][1]);
                }
            }
        }

        // prefetch next K/V tile (hidden under softmax + PV)
        if (t + 1 < S_ / 128) load_tile(t + 1, buf ^ 1);

        // ---- online softmax (rows split across 4 n-warps) ----
        #pragma unroll
        for (int s = 0; s < 8; s++) {
            const int mb = s >> 1, ro = (s & 1) * 2;
            float v = fmaxf(s_acc[mb][0][ro], s_acc[mb][0][ro + 1]);
            #pragma unroll
            for (int nb = 1; nb < 4; nb++)
                v = fmaxf(v, fmaxf(s_acc[mb][nb][ro], s_acc[mb][nb][ro + 1]));
            v = fmaxf(v, __shfl_xor_sync(0xffffffffu, v, 1));
            v = fmaxf(v, __shfl_xor_sync(0xffffffffu, v, 2));
            if (tig == 0) {
                const int row = wm + mb * 16 + g + (s & 1) * 8;
                smf[ORED + row * 4 + (wid & 3)] = v;
            }
        }
        __syncthreads();

        float corr[8], mnew[8];
        #pragma unroll
        for (int s = 0; s < 8; s++) {
            const int row = wm + (s >> 1) * 16 + g + (s & 1) * 8;
            float mx = fmaxf(fmaxf(smf[ORED + row * 4], smf[ORED + row * 4 + 1]),
                             fmaxf(smf[ORED + row * 4 + 2], smf[ORED + row * 4 + 3]));
            mx *= 0.125f;
            mnew[s] = fmaxf(m_r[s], mx);
            corr[s] = __expf(m_r[s] - mnew[s]);
            m_r[s]  = mnew[s];
        }

        #pragma unroll
        for (int s = 0; s < 8; s++) {
            const int mb = s >> 1, ro = (s & 1) * 2;
            float sum = 0.f;
            #pragma unroll
            for (int nb = 0; nb < 4; nb++) {
                float p0 = __expf(s_acc[mb][nb][ro]     * 0.125f - mnew[s]);
                float p1 = __expf(s_acc[mb][nb][ro + 1] * 0.125f - mnew[s]);
                s_acc[mb][nb][ro] = p0; s_acc[mb][nb][ro + 1] = p1;
                sum += p0 + p1;
            }
            sum += __shfl_xor_sync(0xffffffffu, sum, 1);
            sum += __shfl_xor_sync(0xffffffffu, sum, 2);
            if (tig == 0) {
                const int row = wm + mb * 16 + g + (s & 1) * 8;
                smf[ORED + 512 + row * 4 + (wid & 3)] = sum;
            }
        }
        __syncthreads();

        #pragma unroll
        for (int s = 0; s < 8; s++) {
            const int row = wm + (s >> 1) * 16 + g + (s & 1) * 8;
            const float* rs = &smf[ORED + 512 + row * 4];
            l_r[s] = l_r[s] * corr[s] + (rs[0] + rs[1] + rs[2] + rs[3]);
        }
        #pragma unroll
        for (int mb = 0; mb < 4; mb++)
            #pragma unroll
            for (int nb = 0; nb < 2; nb++) {
                o_acc[mb][nb][0] *= corr[mb * 2];
                o_acc[mb][nb][1] *= corr[mb * 2];
                o_acc[mb][nb][2] *= corr[mb * 2 + 1];
                o_acc[mb][nb][3] *= corr[mb * 2 + 1];
            }

        // P (hi only) -> smem [q][kt], stride 68 words
        #pragma unroll
        for (int mb = 0; mb < 4; mb++) {
            const int r0 = wm + mb * 16 + g;
            #pragma unroll
            for (int nb = 0; nb < 4; nb++) {
                const int cp = (wn >> 1) + nb * 4 + tig;
                #pragma unroll
                for (int hf = 0; hf < 2; hf++) {
                    const int r = r0 + hf * 8;
                    *(__half2*)&smv[OPH + r * 68 + cp] =
                        __floats2half2_rn(s_acc[mb][nb][hf * 2],
                                          s_acc[mb][nb][hf * 2 + 1]);
                }
            }
        }
        __syncthreads();

        // ---- O += P V, 2-term (Ph*Vh + Ph*Vl) ----
        const uint32_t vB = sbase + (OV0 + buf * 9216) * 4;
        #pragma unroll
        for (int k = 0; k < 8; k++) {
            uint32_t vh[2][2], vl[2][2];
            const uint32_t vad = vB + vb_off + (k * 16 * 36) * 4;
            LDSM4T(vh[0][0], vh[0][1], vh[1][0], vh[1][1], vad);
            LDSM4T(vl[0][0], vl[0][1], vl[1][0], vl[1][1], vad + 4608 * 4);
            #pragma unroll
            for (int mb = 0; mb < 4; mb++) {
                uint32_t ah[4];
                const uint32_t ad = sbase + OPH * 4 + pa_off
                                    + (mb * 16 * 68 + k * 8) * 4;
                LDSM4(ah[0], ah[1], ah[2], ah[3], ad);
                #pragma unroll
                for (int nb = 0; nb < 2; nb++) {
                    MMA16(o_acc[mb][nb], ah, vh[nb][0], vh[nb][1]);
                    MMA16(o_acc[mb][nb], ah, vl[nb][0], vl[nb][1]);
                }
            }
        }
    }

    // epilogue: normalize, split hi/lo, write [B,S,H,64]
    const int b = bhid >> 4, h = bhid & 15;
    #pragma unroll
    for (int mb = 0; mb < 4; mb++) {
        #pragma unroll
        for (int hf = 0; hf < 2; hf++) {
            const float inv = 1.0f / l_r[mb * 2 + hf];
            const int q = q0 + wm + mb * 16 + g + hf * 8;
            #pragma unroll
            for (int nb = 0; nb < 2; nb++) {
                const int col = wnv + nb * 8 + 2 * tig;
                const float v0 = o_acc[mb][nb][hf * 2]     * inv;
                const float v1 = o_acc[mb][nb][hf * 2 + 1] * inv;
                const size_t idx =
                    (((size_t)b * S_ + q) * N_HEADS + h) * D_K + col;
                __half2 hi2 = __floats2half2_rn(v0, v1);
                float2 hf2 = __half22float2(hi2);
                *(__half2*)&g_Oh[idx] = hi2;
                *(__half2*)&g_Ol[idx] = __floats2half2_rn(v0 - hf2.x, v1 - hf2.y);
            }
        }
    }
}

// ---------------------------------------------------------------------------
extern "C" void kernel_launch(void* const* d_in, const int* in_sizes, int n_in,
                              void* d_out, int out_size)
{
    const float* x  = (const float*)d_in[0];
    const float* Wq = (const float*)d_in[1];
    const float* bq = (const float*)d_in[2];
    const float* Wk = (const float*)d_in[3];
    const float* bk = (const float*)d_in[4];
    const float* Wv = (const float*)d_in[5];
    const float* bv = (const float*)d_in[6];
    const float* Wo = (const float*)d_in[7];
    const float* bo = (const float*)d_in[8];
    float* out = (float*)d_out;

    cudaFuncSetAttribute(gemm_f16, cudaFuncAttributeMaxDynamicSharedMemorySize,
                         GEMM_SMEM);
    cudaFuncSetAttribute(attn_f16, cudaFuncAttributeMaxDynamicSharedMemorySize,
                         ATT_SMEM);

    split_k<<<M_TOT * D_MODEL / 1024, 256>>>((const float4*)x,  0);
    split_k<<<D_MODEL * D_MODEL / 1024, 256>>>((const float4*)Wq, 1);
    split_k<<<D_MODEL * D_MODEL / 1024, 256>>>((const float4*)Wk, 2);
    split_k<<<D_MODEL * D_MODEL / 1024, 256>>>((const float4*)Wv, 3);
    split_k<<<D_MODEL * D_MODEL / 1024, 256>>>((const float4*)Wo, 4);

    gemm_f16<<<dim3(24, M_TOT / 128), 256, GEMM_SMEM>>>(bq, bk, bv, nullptr, 0);

    attn_f16<<<dim3(S_ / 128, BH_), 256, ATT_SMEM>>>();

    gemm_f16<<<dim3(8, M_TOT / 128), 256, GEMM_SMEM>>>(bo, nullptr, nullptr, out, 1);
}

// round 10
// speedup vs baseline: 3.0954x; 1.1161x over previous
#include <cuda_runtime.h>
#include <cuda_fp16.h>
#include <cstdint>

#define D_MODEL 1024
#define N_HEADS 16
#define D_K     64
#define B_      2
#define S_      2048
#define M_TOT   (B_ * S_)
#define BH_     (B_ * N_HEADS)

// ---------------------------------------------------------------------------
// Scratch (allocation-free): fp16 hi/lo operand arrays.
// ---------------------------------------------------------------------------
__device__ __half g_xh[(size_t)M_TOT * D_MODEL], g_xl[(size_t)M_TOT * D_MODEL];
__device__ __half g_Wh[4][(size_t)D_MODEL * D_MODEL];
__device__ __half g_Wl[4][(size_t)D_MODEL * D_MODEL];
// Q/K/V: [B,H,S,64]; O: [B,S,H,64]
__device__ __half g_Qh[(size_t)BH_ * S_ * D_K], g_Ql[(size_t)BH_ * S_ * D_K];
__device__ __half g_Kh[(size_t)BH_ * S_ * D_K], g_Kl[(size_t)BH_ * S_ * D_K];
__device__ __half g_Vh[(size_t)BH_ * S_ * D_K], g_Vl[(size_t)BH_ * S_ * D_K];
__device__ __half g_Oh[(size_t)BH_ * S_ * D_K], g_Ol[(size_t)BH_ * S_ * D_K];

__device__ __forceinline__ uint32_t smem_u32(const void* p) {
    uint32_t a;
    asm("{ .reg .u64 t; cvta.to.shared.u64 t, %1; cvt.u32.u64 %0, t; }"
        : "=r"(a) : "l"(p));
    return a;
}

#define MMA16(d, a, b0, b1)                                                  \
    asm volatile(                                                            \
        "mma.sync.aligned.m16n8k16.row.col.f32.f16.f16.f32 "                 \
        "{%0,%1,%2,%3}, {%4,%5,%6,%7}, {%8,%9}, {%0,%1,%2,%3};"              \
        : "+f"((d)[0]), "+f"((d)[1]), "+f"((d)[2]), "+f"((d)[3])             \
        : "r"((a)[0]), "r"((a)[1]), "r"((a)[2]), "r"((a)[3]),                \
          "r"(b0), "r"(b1))

#define LDSM4(r0, r1, r2, r3, a)                                             \
    asm volatile("ldmatrix.sync.aligned.m8n8.x4.shared.b16 {%0,%1,%2,%3}, [%4];" \
        : "=r"(r0), "=r"(r1), "=r"(r2), "=r"(r3) : "r"(a))
#define LDSM4T(r0, r1, r2, r3, a)                                            \
    asm volatile("ldmatrix.sync.aligned.m8n8.x4.trans.shared.b16 {%0,%1,%2,%3}, [%4];" \
        : "=r"(r0), "=r"(r1), "=r"(r2), "=r"(r3) : "r"(a))

#define CPA16(saddr, gptr)                                                   \
    asm volatile("cp.async.ca.shared.global [%0], [%1], 16;"                 \
                 :: "r"(saddr), "l"(gptr))
#define CPA_COMMIT() asm volatile("cp.async.commit_group;" ::: "memory")
#define CPA_WAIT0()  asm volatile("cp.async.wait_group 0;" ::: "memory")

__device__ __forceinline__ uint32_t packh2(float a, float b) {
    __half2 h = __floats2half2_rn(a, b);
    return *(uint32_t*)&h;
}

// ---------------------------------------------------------------------------
// Split fp32 -> fp16 hi/lo, all 5 tensors in one launch.
// blocks [0,4096): x ; [4096,8192): W[(b-4096)>>10].
// ---------------------------------------------------------------------------
__global__ void __launch_bounds__(256) split_all(
    const float4* __restrict__ x,  const float4* __restrict__ w0,
    const float4* __restrict__ w1, const float4* __restrict__ w2,
    const float4* __restrict__ w3)
{
    const int bi = blockIdx.x;
    const float4* src; __half2 *hi, *lo; int i;
    if (bi < 4096) {
        src = x; hi = (__half2*)g_xh; lo = (__half2*)g_xl;
        i = bi * 256 + threadIdx.x;
    } else {
        const int w = (bi - 4096) >> 10;
        const float4* ws[4] = {w0, w1, w2, w3};
        src = ws[w]; hi = (__half2*)g_Wh[w]; lo = (__half2*)g_Wl[w];
        i = ((bi - 4096) & 1023) * 256 + threadIdx.x;
    }
    float4 v = src[i];
    __half2 h0 = __floats2half2_rn(v.x, v.y);
    __half2 h1 = __floats2half2_rn(v.z, v.w);
    float2 f0 = __half22float2(h0), f1 = __half22float2(h1);
    hi[i * 2]     = h0;
    hi[i * 2 + 1] = h1;
    lo[i * 2]     = __floats2half2_rn(v.x - f0.x, v.y - f0.y);
    lo[i * 2 + 1] = __floats2half2_rn(v.z - f1.x, v.w - f1.y);
}

// ---------------------------------------------------------------------------
// fp16 3-term GEMM, BK=32, ldmatrix fragments, cp.async double buffer.
// mode 0: fused QKV, grid (24, 32), target = bx>>3. Q epilogue folds 1/8.
// mode 1: out-proj, grid (8, 32), A = g_O, writes fp32 out.
// ---------------------------------------------------------------------------
#define GSTR  20
#define GTILE (128 * GSTR)
#define GBUF  (4 * GTILE)
#define GEMM_SMEM (2 * GBUF * 4)  // 81920 B

__global__ void __launch_bounds__(256, 2) gemm_f16(
    const float* __restrict__ b0p, const float* __restrict__ b1p,
    const float* __restrict__ b2p, float* __restrict__ outp, int mode)
{
    extern __shared__ uint32_t smv[];
    const int tid = threadIdx.x;
    const int wid = tid >> 5, lane = tid & 31;
    const int g   = lane >> 2, tig = lane & 3;
    const int wm  = (wid >> 2) * 64;
    const int wn  = (wid & 3) * 32;
    const int bx = blockIdx.x;
    const int m0 = blockIdx.y * 128;
    const int target = mode ? 3 : (bx >> 3);
    const int n0 = (mode ? bx : (bx & 7)) * 128;

    const __half* Ah = mode ? g_Oh : g_xh;
    const __half* Al = mode ? g_Ol : g_xl;
    const __half* Wh = g_Wh[target];
    const __half* Wl = g_Wl[target];
    const float* bias = mode ? b0p
                             : (target == 0 ? b0p : target == 1 ? b1p : b2p);
    __half *oh = nullptr, *ol = nullptr;
    if (target == 0)      { oh = g_Qh; ol = g_Ql; }
    else if (target == 1) { oh = g_Kh; ol = g_Kl; }
    else if (target == 2) { oh = g_Vh; ol = g_Vl; }
    const bool hs = (mode == 0);
    const float sc = (mode == 0 && target == 0) ? 0.125f : 1.0f;

    const int arr = tid >> 6, t = tid & 63;
    const __half* srcs[4] = {Ah, Al, Wh, Wl};
    const int rb = (arr < 2) ? m0 : n0;
    const __half* sp = srcs[arr] + (size_t)(rb + t) * D_MODEL;
    const uint32_t sbase = smem_u32(smv);
    const uint32_t sdst = sbase + (uint32_t)(arr * GTILE + t * GSTR) * 4;

    float acc[4][4][4];
    #pragma unroll
    for (int i = 0; i < 4; i++)
        #pragma unroll
        for (int j = 0; j < 4; j++)
            acc[i][j][0] = acc[i][j][1] = acc[i][j][2] = acc[i][j][3] = 0.f;

    #pragma unroll
    for (int r = 0; r < 2; r++)
        #pragma unroll
        for (int j = 0; j < 4; j++)
            CPA16(sdst + r * 64 * GSTR * 4 + j * 16,
                  sp + (size_t)r * 64 * D_MODEL + j * 8);
    CPA_COMMIT();

    const uint32_t a_off = ((wm + (lane & 15)) * GSTR + ((lane >> 4) << 2)) * 4;
    const uint32_t b_off = ((wn + (lane & 7) + ((lane >> 4) << 3)) * GSTR
                            + (((lane >> 3) & 1) << 2)) * 4;

    for (int c = 0; c < 32; c++) {
        const int buf = c & 1;
        CPA_WAIT0();
        __syncthreads();
        if (c + 1 < 32) {
            const uint32_t bo = (buf ^ 1) * GBUF * 4;
            const __half* s0 = sp + (c + 1) * 32;
            #pragma unroll
            for (int r = 0; r < 2; r++)
                #pragma unroll
                for (int j = 0; j < 4; j++)
                    CPA16(sdst + bo + r * 64 * GSTR * 4 + j * 16,
                          s0 + (size_t)r * 64 * D_MODEL + j * 8);
            CPA_COMMIT();
        }
        const uint32_t Bb = sbase + buf * GBUF * 4;
        #pragma unroll
        for (int st = 0; st < 2; st++) {
            uint32_t bh[4][2], bl[4][2];
            #pragma unroll
            for (int p = 0; p < 2; p++) {
                uint32_t ad = Bb + 2 * GTILE * 4 + b_off
                              + (p * 16 * GSTR + st * 8) * 4;
                LDSM4(bh[2*p][0], bh[2*p][1], bh[2*p+1][0], bh[2*p+1][1], ad);
                LDSM4(bl[2*p][0], bl[2*p][1], bl[2*p+1][0], bl[2*p+1][1],
                      ad + GTILE * 4);
            }
            #pragma unroll
            for (int mb = 0; mb < 4; mb++) {
                uint32_t ah[4], al[4];
                const uint32_t ad = Bb + a_off + (mb * 16 * GSTR + st * 8) * 4;
                LDSM4(ah[0], ah[1], ah[2], ah[3], ad);
                LDSM4(al[0], al[1], al[2], al[3], ad + GTILE * 4);
                #pragma unroll
                for (int nb = 0; nb < 4; nb++) {
                    MMA16(acc[mb][nb], ah, bh[nb][0], bh[nb][1]);
                    MMA16(acc[mb][nb], ah, bl[nb][0], bl[nb][1]);
                    MMA16(acc[mb][nb], al, bh[nb][0], bh[nb][1]);
                }
            }
        }
    }

    #pragma unroll
    for (int nb = 0; nb < 4; nb++) {
        const int col = n0 + wn + nb * 8 + 2 * tig;
        const float b0 = bias[col], b1 = bias[col + 1];
        #pragma unroll
        for (int mb = 0; mb < 4; mb++) {
            const int row0 = m0 + wm + mb * 16 + g;
            #pragma unroll
            for (int hf = 0; hf < 2; hf++) {
                const int row = row0 + hf * 8;
                const float v0 = (acc[mb][nb][hf * 2]     + b0) * sc;
                const float v1 = (acc[mb][nb][hf * 2 + 1] + b1) * sc;
                if (hs) {
                    const int h = col >> 6, d0 = col & 63;
                    const int bb = row >> 11, ss = row & (S_ - 1);
                    const size_t idx =
                        (((size_t)bb * N_HEADS + h) * S_ + ss) * D_K + d0;
                    __half2 hi2 = __floats2half2_rn(v0, v1);
                    float2 hf2 = __half22float2(hi2);
                    *(__half2*)&oh[idx] = hi2;
                    *(__half2*)&ol[idx] = __floats2half2_rn(v0 - hf2.x, v1 - hf2.y);
                } else {
                    *(float2*)&outp[(size_t)row * D_MODEL + col] =
                        make_float2(v0, v1);
                }
            }
        }
    }
}

// ---------------------------------------------------------------------------
// Flash attention, FA2 layout: 8 warps x 16 q-rows, each warp spans the full
// 128-kt tile. Softmax fully warp-local; S C-frags reused as PV A-frags in
// registers. One __syncthreads per tile. cp.async double-buffered K/V.
// Q scale (1/8) pre-folded by the Q projection.
// ---------------------------------------------------------------------------
#define OQH  0
#define OQL  4608
#define OK0  9216          // + buf*9216 + arr*4608 + row*36
#define OV0  27648
#define ATT_SMEM (46080 * 4)   // 184320 B

__global__ void __launch_bounds__(256, 1) attn_f16()
{
    extern __shared__ uint32_t smv[];
    const int tid  = threadIdx.x;
    const int wid  = tid >> 5, lane = tid & 31;
    const int g    = lane >> 2;
    const int tig  = lane & 3;
    const int wm   = wid * 16;
    const int q0 = blockIdx.x * 128;
    const int bhid = blockIdx.y;
    const size_t hb = (size_t)bhid * S_ * D_K;
    const uint32_t sbase = smem_u32(smv);

    // Q tile load (hi+lo) into smem, one 64-half row per thread.
    {
        const int row = tid >> 1, ar = tid & 1;
        const __half* src = (ar ? g_Ql : g_Qh) + hb + (size_t)(q0 + row) * D_K;
        uint32_t* dst = smv + (ar ? OQL : OQH) + row * 36;
        #pragma unroll
        for (int s2 = 0; s2 < 8; s2++)
            *(uint4*)(dst + s2 * 4) = *(const uint4*)(src + s2 * 8);
    }

    // K/V cp.async loader: arr 0..3 = Kh,Kl,Vh,Vl; rows lrow, lrow+64; 128 B rows.
    const __half* kvsrc0[4] = {g_Kh + hb, g_Kl + hb, g_Vh + hb, g_Vl + hb};
    const int larr = tid >> 6, lrow = tid & 63;
    const __half* lsp = kvsrc0[larr] + (size_t)lrow * D_K;
    const uint32_t ldst = sbase +
        (uint32_t)((larr < 2 ? OK0 : OV0) + (larr & 1) * 4608 + lrow * 36) * 4;

    auto load_tile = [&](int tt, int buf) {
        const __half* s0 = lsp + (size_t)tt * 128 * D_K;
        const uint32_t d0 = ldst + buf * 9216 * 4;
        #pragma unroll
        for (int r = 0; r < 2; r++)
            #pragma unroll
            for (int j = 0; j < 8; j++)
                CPA16(d0 + r * 64 * 36 * 4 + j * 16,
                      s0 + (size_t)r * 64 * D_K + j * 8);
        CPA_COMMIT();
    };

    load_tile(0, 0);
    __syncthreads();   // Q smem visible

    // Q fragments resident in registers for the whole kernel.
    uint32_t qh[4][4], ql[4][4];
    {
        const uint32_t qa_off = ((wm + (lane & 15)) * 36
                                 + ((lane >> 4) << 2)) * 4;
        #pragma unroll
        for (int st = 0; st < 4; st++) {
            const uint32_t ad = sbase + qa_off + (st * 8) * 4;
            LDSM4(qh[st][0], qh[st][1], qh[st][2], qh[st][3], ad);
            LDSM4(ql[st][0], ql[st][1], ql[st][2], ql[st][3], ad + OQL * 4);
        }
    }

    const uint32_t kb_off = (((lane & 7) + ((lane >> 4) << 3)) * 36
                             + (((lane >> 3) & 1) << 2)) * 4;
    const uint32_t vb_off = (((lane & 7) + (((lane >> 3) & 1) << 3)) * 36
                             + ((lane >> 4) << 2)) * 4;

    float m_r[2] = {-1e30f, -1e30f}, l_r[2] = {0.f, 0.f};
    float o_acc[8][4];
    #pragma unroll
    for (int nb = 0; nb < 8; nb++)
        o_acc[nb][0] = o_acc[nb][1] = o_acc[nb][2] = o_acc[nb][3] = 0.f;

    for (int t = 0; t < S_ / 128; t++) {
        const int buf = t & 1;
        CPA_WAIT0();
        __syncthreads();

        // ---- S = Q K^T, 3-term; warp covers 16 q x 128 kt ----
        float s_acc[16][4];
        #pragma unroll
        for (int nb = 0; nb < 16; nb++)
            s_acc[nb][0] = s_acc[nb][1] = s_acc[nb][2] = s_acc[nb][3] = 0.f;

        const uint32_t kB = sbase + (OK0 + buf * 9216) * 4;
        #pragma unroll
        for (int st = 0; st < 4; st++) {
            #pragma unroll
            for (int p = 0; p < 8; p++) {
                uint32_t bh[4], bl[4];
                const uint32_t ad = kB + kb_off + (p * 16 * 36 + st * 8) * 4;
                LDSM4(bh[0], bh[1], bh[2], bh[3], ad);
                LDSM4(bl[0], bl[1], bl[2], bl[3], ad + 4608 * 4);
                MMA16(s_acc[2*p],   qh[st], bh[0], bh[1]);
                MMA16(s_acc[2*p],   ql[st], bh[0], bh[1]);
                MMA16(s_acc[2*p],   qh[st], bl[0], bl[1]);
                MMA16(s_acc[2*p+1], qh[st], bh[2], bh[3]);
                MMA16(s_acc[2*p+1], ql[st], bh[2], bh[3]);
                MMA16(s_acc[2*p+1], qh[st], bl[2], bl[3]);
            }
        }

        // prefetch next K/V tile (other buffer; no hazard with current reads)
        if (t + 1 < S_ / 128) load_tile(t + 1, buf ^ 1);

        // ---- warp-local online softmax (rows g and g+8) ----
        float mx0 = -1e30f, mx1 = -1e30f;
        #pragma unroll
        for (int nb = 0; nb < 16; nb++) {
            mx0 = fmaxf(mx0, fmaxf(s_acc[nb][0], s_acc[nb][1]));
            mx1 = fmaxf(mx1, fmaxf(s_acc[nb][2], s_acc[nb][3]));
        }
        mx0 = fmaxf(mx0, __shfl_xor_sync(0xffffffffu, mx0, 1));
        mx0 = fmaxf(mx0, __shfl_xor_sync(0xffffffffu, mx0, 2));
        mx1 = fmaxf(mx1, __shfl_xor_sync(0xffffffffu, mx1, 1));
        mx1 = fmaxf(mx1, __shfl_xor_sync(0xffffffffu, mx1, 2));

        const float mn0 = fmaxf(m_r[0], mx0), mn1 = fmaxf(m_r[1], mx1);
        const float c0 = __expf(m_r[0] - mn0), c1 = __expf(m_r[1] - mn1);
        m_r[0] = mn0; m_r[1] = mn1;

        float sum0 = 0.f, sum1 = 0.f;
        #pragma unroll
        for (int nb = 0; nb < 16; nb++) {
            float p0 = __expf(s_acc[nb][0] - mn0);
            float p1 = __expf(s_acc[nb][1] - mn0);
            float p2 = __expf(s_acc[nb][2] - mn1);
            float p3 = __expf(s_acc[nb][3] - mn1);
            s_acc[nb][0] = p0; s_acc[nb][1] = p1;
            s_acc[nb][2] = p2; s_acc[nb][3] = p3;
            sum0 += p0 + p1; sum1 += p2 + p3;
        }
        sum0 += __shfl_xor_sync(0xffffffffu, sum0, 1);
        sum0 += __shfl_xor_sync(0xffffffffu, sum0, 2);
        sum1 += __shfl_xor_sync(0xffffffffu, sum1, 1);
        sum1 += __shfl_xor_sync(0xffffffffu, sum1, 2);
        l_r[0] = l_r[0] * c0 + sum0;
        l_r[1] = l_r[1] * c1 + sum1;

        #pragma unroll
        for (int nb = 0; nb < 8; nb++) {
            o_acc[nb][0] *= c0; o_acc[nb][1] *= c0;
            o_acc[nb][2] *= c1; o_acc[nb][3] *= c1;
        }

        // ---- O += P V; P C-frags -> A-frags in registers ----
        const uint32_t vB = sbase + (OV0 + buf * 9216) * 4;
        #pragma unroll
        for (int kk = 0; kk < 8; kk++) {
            uint32_t pa[4];
            pa[0] = packh2(s_acc[2*kk][0],   s_acc[2*kk][1]);
            pa[1] = packh2(s_acc[2*kk][2],   s_acc[2*kk][3]);
            pa[2] = packh2(s_acc[2*kk+1][0], s_acc[2*kk+1][1]);
            pa[3] = packh2(s_acc[2*kk+1][2], s_acc[2*kk+1][3]);
            #pragma unroll
            for (int dp = 0; dp < 4; dp++) {
                uint32_t vh[4], vl[4];
                const uint32_t vad = vB + vb_off + (kk * 16 * 36 + dp * 8) * 4;
                LDSM4T(vh[0], vh[1], vh[2], vh[3], vad);
                LDSM4T(vl[0], vl[1], vl[2], vl[3], vad + 4608 * 4);
                MMA16(o_acc[2*dp],   pa, vh[0], vh[1]);
                MMA16(o_acc[2*dp],   pa, vl[0], vl[1]);
                MMA16(o_acc[2*dp+1], pa, vh[2], vh[3]);
                MMA16(o_acc[2*dp+1], pa, vl[2], vl[3]);
            }
        }
    }

    // ---- epilogue: normalize, split hi/lo, write [B,S,H,64] ----
    const int b = bhid >> 4, h = bhid & 15;
    const float inv0 = 1.0f / l_r[0], inv1 = 1.0f / l_r[1];
    const int qrow = q0 + wm + g;
    #pragma unroll
    for (int nb = 0; nb < 8; nb++) {
        const int col = nb * 8 + 2 * tig;
        {
            const float v0 = o_acc[nb][0] * inv0, v1 = o_acc[nb][1] * inv0;
            const size_t idx = (((size_t)b * S_ + qrow) * N_HEADS + h) * D_K + col;
            __half2 hi2 = __floats2half2_rn(v0, v1);
            float2 hf2 = __half22float2(hi2);
            *(__half2*)&g_Oh[idx] = hi2;
            *(__half2*)&g_Ol[idx] = __floats2half2_rn(v0 - hf2.x, v1 - hf2.y);
        }
        {
            const float v0 = o_acc[nb][2] * inv1, v1 = o_acc[nb][3] * inv1;
            const size_t idx = (((size_t)b * S_ + qrow + 8) * N_HEADS + h) * D_K + col;
            __half2 hi2 = __floats2half2_rn(v0, v1);
            float2 hf2 = __half22float2(hi2);
            *(__half2*)&g_Oh[idx] = hi2;
            *(__half2*)&g_Ol[idx] = __floats2half2_rn(v0 - hf2.x, v1 - hf2.y);
        }
    }
}

// ---------------------------------------------------------------------------
extern "C" void kernel_launch(void* const* d_in, const int* in_sizes, int n_in,
                              void* d_out, int out_size)
{
    const float* x  = (const float*)d_in[0];
    const float* Wq = (const float*)d_in[1];
    const float* bq = (const float*)d_in[2];
    const float* Wk = (const float*)d_in[3];
    const float* bk = (const float*)d_in[4];
    const float* Wv = (const float*)d_in[5];
    const float* bv = (const float*)d_in[6];
    const float* Wo = (const float*)d_in[7];
    const float* bo = (const float*)d_in[8];
    float* out = (float*)d_out;

    cudaFuncSetAttribute(gemm_f16, cudaFuncAttributeMaxDynamicSharedMemorySize,
                         GEMM_SMEM);
    cudaFuncSetAttribute(attn_f16, cudaFuncAttributeMaxDynamicSharedMemorySize,
                         ATT_SMEM);

    split_all<<<8192, 256>>>((const float4*)x, (const float4*)Wq,
                             (const float4*)Wk, (const float4*)Wv,
                             (const float4*)Wo);

    gemm_f16<<<dim3(24, M_TOT / 128), 256, GEMM_SMEM>>>(bq, bk, bv, nullptr, 0);

    attn_f16<<<dim3(S_ / 128, BH_), 256, ATT_SMEM>>>();

    gemm_f16<<<dim3(8, M_TOT / 128), 256, GEMM_SMEM>>>(bo, nullptr, nullptr, out, 1);
}

// round 12
// speedup vs baseline: 4.4036x; 1.4226x over previous
#include <cuda_runtime.h>
#include <cuda_fp16.h>
#include <cstdint>

#define D_MODEL 1024
#define N_HEADS 16
#define D_K     64
#define B_      2
#define S_      2048
#define M_TOT   (B_ * S_)
#define BH_     (B_ * N_HEADS)

// ---------------------------------------------------------------------------
// Scratch: x hi-only; W hi+lo; Q hi+lo; K hi-only; V hi+lo; O hi-only.
// ---------------------------------------------------------------------------
__device__ __half g_xh[(size_t)M_TOT * D_MODEL];
__device__ __half g_Wh[4][(size_t)D_MODEL * D_MODEL];
__device__ __half g_Wl[4][(size_t)D_MODEL * D_MODEL];
__device__ __half g_Qh[(size_t)BH_ * S_ * D_K], g_Ql[(size_t)BH_ * S_ * D_K];
__device__ __half g_Kh[(size_t)BH_ * S_ * D_K];
__device__ __half g_Vh[(size_t)BH_ * S_ * D_K], g_Vl[(size_t)BH_ * S_ * D_K];
__device__ __half g_Oh[(size_t)BH_ * S_ * D_K];

__device__ __forceinline__ uint32_t smem_u32(const void* p) {
    uint32_t a;
    asm("{ .reg .u64 t; cvta.to.shared.u64 t, %1; cvt.u32.u64 %0, t; }"
        : "=r"(a) : "l"(p));
    return a;
}

#define MMA16(d, a, b0, b1)                                                  \
    asm volatile(                                                            \
        "mma.sync.aligned.m16n8k16.row.col.f32.f16.f16.f32 "                 \
        "{%0,%1,%2,%3}, {%4,%5,%6,%7}, {%8,%9}, {%0,%1,%2,%3};"              \
        : "+f"((d)[0]), "+f"((d)[1]), "+f"((d)[2]), "+f"((d)[3])             \
        : "r"((a)[0]), "r"((a)[1]), "r"((a)[2]), "r"((a)[3]),                \
          "r"(b0), "r"(b1))

#define LDSM4(r0, r1, r2, r3, a)                                             \
    asm volatile("ldmatrix.sync.aligned.m8n8.x4.shared.b16 {%0,%1,%2,%3}, [%4];" \
        : "=r"(r0), "=r"(r1), "=r"(r2), "=r"(r3) : "r"(a))
#define LDSM4T(r0, r1, r2, r3, a)                                            \
    asm volatile("ldmatrix.sync.aligned.m8n8.x4.trans.shared.b16 {%0,%1,%2,%3}, [%4];" \
        : "=r"(r0), "=r"(r1), "=r"(r2), "=r"(r3) : "r"(a))

#define CPA16(saddr, gptr)                                                   \
    asm volatile("cp.async.ca.shared.global [%0], [%1], 16;"                 \
                 :: "r"(saddr), "l"(gptr))
#define CPA_COMMIT() asm volatile("cp.async.commit_group;" ::: "memory")
#define CPA_WAIT0()  asm volatile("cp.async.wait_group 0;" ::: "memory")

__device__ __forceinline__ uint32_t packh2(float a, float b) {
    __half2 h = __floats2half2_rn(a, b);
    return *(uint32_t*)&h;
}

// ---------------------------------------------------------------------------
// Split: x -> hi only; W -> hi+lo. Grid 8192: [0,4096)=x, rest W[(b-4096)>>10].
// ---------------------------------------------------------------------------
__global__ void __launch_bounds__(256) split_all(
    const float4* __restrict__ x,  const float4* __restrict__ w0,
    const float4* __restrict__ w1, const float4* __restrict__ w2,
    const float4* __restrict__ w3)
{
    const int bi = blockIdx.x;
    if (bi < 4096) {
        const int i = bi * 256 + threadIdx.x;
        float4 v = x[i];
        __half2* hi = (__half2*)g_xh;
        hi[i * 2]     = __floats2half2_rn(v.x, v.y);
        hi[i * 2 + 1] = __floats2half2_rn(v.z, v.w);
        return;
    }
    const int w = (bi - 4096) >> 10;
    const float4* ws[4] = {w0, w1, w2, w3};
    const int i = ((bi - 4096) & 1023) * 256 + threadIdx.x;
    float4 v = ws[w][i];
    __half2* hi = (__half2*)g_Wh[w];
    __half2* lo = (__half2*)g_Wl[w];
    __half2 h0 = __floats2half2_rn(v.x, v.y);
    __half2 h1 = __floats2half2_rn(v.z, v.w);
    float2 f0 = __half22float2(h0), f1 = __half22float2(h1);
    hi[i * 2]     = h0;
    hi[i * 2 + 1] = h1;
    lo[i * 2]     = __floats2half2_rn(v.x - f0.x, v.y - f0.y);
    lo[i * 2 + 1] = __floats2half2_rn(v.z - f1.x, v.w - f1.y);
}

// ---------------------------------------------------------------------------
// 2-term GEMM: C = Ah @ (Wh + Wl)^T + bias. BK=32, cp.async double buffer.
// Smem arrays per buffer: Ah(0), Bh(GTILE), Bl(2*GTILE); stride 20 words.
// mode 0: fused QKV grid (24,32); mode 1: out-proj grid (8,32) fp32 out.
// Epilogues: Q -> Qh+Ql (x0.125 folded); K -> Kh only; V -> Vh+Vl.
// ---------------------------------------------------------------------------
#define GSTR  20
#define GTILE (128 * GSTR)
#define GBUF  (3 * GTILE)
#define GEMM_SMEM (2 * GBUF * 4)  // 61440 B

__global__ void __launch_bounds__(256, 2) gemm_f16(
    const float* __restrict__ b0p, const float* __restrict__ b1p,
    const float* __restrict__ b2p, float* __restrict__ outp, int mode)
{
    extern __shared__ uint32_t smv[];
    const int tid = threadIdx.x;
    const int wid = tid >> 5, lane = tid & 31;
    const int g   = lane >> 2, tig = lane & 3;
    const int wm  = (wid >> 2) * 64;
    const int wn  = (wid & 3) * 32;
    const int bx = blockIdx.x;
    const int m0 = blockIdx.y * 128;
    const int target = mode ? 3 : (bx >> 3);
    const int n0 = (mode ? bx : (bx & 7)) * 128;

    const __half* Ah = mode ? g_Oh : g_xh;
    const __half* Wh = g_Wh[target];
    const __half* Wl = g_Wl[target];
    const float* bias = mode ? b0p
                             : (target == 0 ? b0p : target == 1 ? b1p : b2p);
    __half *oh = nullptr, *ol = nullptr;
    if (target == 0)      { oh = g_Qh; ol = g_Ql; }
    else if (target == 1) { oh = g_Kh; ol = nullptr; }
    else if (target == 2) { oh = g_Vh; ol = g_Vl; }
    const bool hs = (mode == 0);
    const float sc = (mode == 0 && target == 0) ? 0.125f : 1.0f;

    const uint32_t sbase = smem_u32(smv);

    // loaders: group 0 -> Ah row lt; group 1 -> Bh row lt (4 x 16B each);
    // all threads -> 2 Bl chunks (c = tid*2+i: row c>>2, j c&3).
    const int gsel = tid >> 7, lt = tid & 127;
    const __half* spAB = (gsel == 0 ? Ah + (size_t)(m0 + lt) * D_MODEL
                                    : Wh + (size_t)(n0 + lt) * D_MODEL);
    const uint32_t dAB = sbase + (uint32_t)((gsel ? GTILE : 0) + lt * GSTR) * 4;
    const int blr0 = (tid * 2) >> 2, blj0 = (tid * 2) & 3;
    const int blr1 = (tid * 2 + 1) >> 2, blj1 = (tid * 2 + 1) & 3;
    const __half* blsrc0 = Wl + (size_t)(n0 + blr0) * D_MODEL + blj0 * 8;
    const __half* blsrc1 = Wl + (size_t)(n0 + blr1) * D_MODEL + blj1 * 8;
    const uint32_t bld0 = sbase + (uint32_t)(2 * GTILE + blr0 * GSTR) * 4 + blj0 * 16;
    const uint32_t bld1 = sbase + (uint32_t)(2 * GTILE + blr1 * GSTR) * 4 + blj1 * 16;

    auto load_chunk = [&](int kc, int buf) {
        const uint32_t bo = buf * GBUF * 4;
        const __half* s0 = spAB + kc * 32;
        #pragma unroll
        for (int j = 0; j < 4; j++)
            CPA16(dAB + bo + j * 16, s0 + j * 8);
        CPA16(bld0 + bo, blsrc0 + kc * 32);
        CPA16(bld1 + bo, blsrc1 + kc * 32);
        CPA_COMMIT();
    };

    float acc[4][4][4];
    #pragma unroll
    for (int i = 0; i < 4; i++)
        #pragma unroll
        for (int j = 0; j < 4; j++)
            acc[i][j][0] = acc[i][j][1] = acc[i][j][2] = acc[i][j][3] = 0.f;

    load_chunk(0, 0);

    const uint32_t a_off = ((wm + (lane & 15)) * GSTR + ((lane >> 4) << 2)) * 4;
    const uint32_t b_off = ((wn + (lane & 7) + ((lane >> 4) << 3)) * GSTR
                            + (((lane >> 3) & 1) << 2)) * 4;

    for (int c = 0; c < 32; c++) {
        const int buf = c & 1;
        CPA_WAIT0();
        __syncthreads();
        if (c + 1 < 32) load_chunk(c + 1, buf ^ 1);

        const uint32_t Bb = sbase + buf * GBUF * 4;
        #pragma unroll
        for (int st = 0; st < 2; st++) {
            uint32_t bh[4][2], bl[4][2];
            #pragma unroll
            for (int p = 0; p < 2; p++) {
                const uint32_t ad = Bb + GTILE * 4 + b_off
                                    + (p * 16 * GSTR + st * 8) * 4;
                LDSM4(bh[2*p][0], bh[2*p][1], bh[2*p+1][0], bh[2*p+1][1], ad);
                LDSM4(bl[2*p][0], bl[2*p][1], bl[2*p+1][0], bl[2*p+1][1],
                      ad + GTILE * 4);
            }
            #pragma unroll
            for (int mb = 0; mb < 4; mb++) {
                uint32_t ah[4];
                const uint32_t ad = Bb + a_off + (mb * 16 * GSTR + st * 8) * 4;
                LDSM4(ah[0], ah[1], ah[2], ah[3], ad);
                #pragma unroll
                for (int nb = 0; nb < 4; nb++) {
                    MMA16(acc[mb][nb], ah, bh[nb][0], bh[nb][1]);
                    MMA16(acc[mb][nb], ah, bl[nb][0], bl[nb][1]);
                }
            }
        }
    }

    #pragma unroll
    for (int nb = 0; nb < 4; nb++) {
        const int col = n0 + wn + nb * 8 + 2 * tig;
        const float b0 = bias[col], b1 = bias[col + 1];
        #pragma unroll
        for (int mb = 0; mb < 4; mb++) {
            const int row0 = m0 + wm + mb * 16 + g;
            #pragma unroll
            for (int hf = 0; hf < 2; hf++) {
                const int row = row0 + hf * 8;
                const float v0 = (acc[mb][nb][hf * 2]     + b0) * sc;
                const float v1 = (acc[mb][nb][hf * 2 + 1] + b1) * sc;
                if (hs) {
                    const int h = col >> 6, d0 = col & 63;
                    const int bb = row >> 11, ss = row & (S_ - 1);
                    const size_t idx =
                        (((size_t)bb * N_HEADS + h) * S_ + ss) * D_K + d0;
                    __half2 hi2 = __floats2half2_rn(v0, v1);
                    *(__half2*)&oh[idx] = hi2;
                    if (ol) {
                        float2 hf2 = __half22float2(hi2);
                        *(__half2*)&ol[idx] =
                            __floats2half2_rn(v0 - hf2.x, v1 - hf2.y);
                    }
                } else {
                    *(float2*)&outp[(size_t)row * D_MODEL + col] =
                        make_float2(v0, v1);
                }
            }
        }
    }
}

// ---------------------------------------------------------------------------
// Flash attention, FA2 layout (8 warps x 16 q-rows). S = (Qh+Ql)·Kh (2-term),
// PV = Ph·(Vh+Vl) (2-term). K hi-only. cp.async double-buffered K/V.
// Smem (words): Qh 0, Ql 4608, then per buf (stride 13824): Kh +0, Vh +4608,
// Vl +9216. Total (9216 + 2*13824)*4 = 147456 B.
// ---------------------------------------------------------------------------
#define OQH  0
#define OQL  4608
#define OKV0 9216
#define PBUF 13824
#define ATT_SMEM ((OKV0 + 2 * PBUF) * 4)   // 147456 B

__global__ void __launch_bounds__(256, 1) attn_f16()
{
    extern __shared__ uint32_t smv[];
    const int tid  = threadIdx.x;
    const int wid  = tid >> 5, lane = tid & 31;
    const int g    = lane >> 2;
    const int tig  = lane & 3;
    const int wm   = wid * 16;
    const int q0 = blockIdx.x * 128;
    const int bhid = blockIdx.y;
    const size_t hb = (size_t)bhid * S_ * D_K;
    const uint32_t sbase = smem_u32(smv);

    // Q tile load (hi+lo), one 64-half row per thread.
    {
        const int row = tid >> 1, ar = tid & 1;
        const __half* src = (ar ? g_Ql : g_Qh) + hb + (size_t)(q0 + row) * D_K;
        uint32_t* dst = smv + (ar ? OQL : OQH) + row * 36;
        #pragma unroll
        for (int s2 = 0; s2 < 8; s2++)
            *(uint4*)(dst + s2 * 4) = *(const uint4*)(src + s2 * 8);
    }

    // K/V cp.async loader: group 0 -> Kh row lt, group 1 -> Vh row lt
    // (8 x 16B per 128B row); all threads -> 4 Vl chunks.
    const int gsel = tid >> 7, lt = tid & 127;
    const __half* kvsrc = (gsel == 0 ? g_Kh : g_Vh) + hb + (size_t)lt * D_K;
    const uint32_t kvoff = (uint32_t)((gsel ? 4608 : 0) + lt * 36) * 4;
    const int vc0 = tid * 4;
    const __half* vlb = g_Vl + hb;

    auto load_tile = [&](int tt, int buf) {
        const uint32_t base = sbase + (OKV0 + buf * PBUF) * 4;
        const __half* s0 = kvsrc + (size_t)tt * 128 * D_K;
        #pragma unroll
        for (int j = 0; j < 8; j++)
            CPA16(base + kvoff + j * 16, s0 + j * 8);
        #pragma unroll
        for (int i = 0; i < 4; i++) {
            const int c = vc0 + i, row = c >> 3, j = c & 7;
            CPA16(base + (uint32_t)(9216 + row * 36) * 4 + j * 16,
                  vlb + (size_t)(tt * 128 + row) * D_K + j * 8);
        }
        CPA_COMMIT();
    };

    load_tile(0, 0);
    __syncthreads();   // Q smem visible

    // Q fragments resident in registers.
    uint32_t qh[4][4], ql[4][4];
    {
        const uint32_t qa_off = ((wm + (lane & 15)) * 36
                                 + ((lane >> 4) << 2)) * 4;
        #pragma unroll
        for (int st = 0; st < 4; st++) {
            const uint32_t ad = sbase + qa_off + (st * 8) * 4;
            LDSM4(qh[st][0], qh[st][1], qh[st][2], qh[st][3], ad);
            LDSM4(ql[st][0], ql[st][1], ql[st][2], ql[st][3], ad + OQL * 4);
        }
    }

    const uint32_t kb_off = (((lane & 7) + ((lane >> 4) << 3)) * 36
                             + (((lane >> 3) & 1) << 2)) * 4;
    const uint32_t vb_off = (((lane & 7) + (((lane >> 3) & 1) << 3)) * 36
                             + ((lane >> 4) << 2)) * 4;

    float m_r[2] = {-1e30f, -1e30f}, l_r[2] = {0.f, 0.f};
    float o_acc[8][4];
    #pragma unroll
    for (int nb = 0; nb < 8; nb++)
        o_acc[nb][0] = o_acc[nb][1] = o_acc[nb][2] = o_acc[nb][3] = 0.f;

    for (int t = 0; t < S_ / 128; t++) {
        const int buf = t & 1;
        CPA_WAIT0();
        __syncthreads();

        // ---- S = (Qh+Ql) Kh^T ----
        float s_acc[16][4];
        #pragma unroll
        for (int nb = 0; nb < 16; nb++)
            s_acc[nb][0] = s_acc[nb][1] = s_acc[nb][2] = s_acc[nb][3] = 0.f;

        const uint32_t kB = sbase + (OKV0 + buf * PBUF) * 4;
        #pragma unroll
        for (int st = 0; st < 4; st++) {
            #pragma unroll
            for (int p = 0; p < 8; p++) {
                uint32_t bh[4];
                const uint32_t ad = kB + kb_off + (p * 16 * 36 + st * 8) * 4;
                LDSM4(bh[0], bh[1], bh[2], bh[3], ad);
                MMA16(s_acc[2*p],   qh[st], bh[0], bh[1]);
                MMA16(s_acc[2*p],   ql[st], bh[0], bh[1]);
                MMA16(s_acc[2*p+1], qh[st], bh[2], bh[3]);
                MMA16(s_acc[2*p+1], ql[st], bh[2], bh[3]);
            }
        }

        if (t + 1 < S_ / 128) load_tile(t + 1, buf ^ 1);

        // ---- warp-local online softmax (rows g and g+8) ----
        float mx0 = -1e30f, mx1 = -1e30f;
        #pragma unroll
        for (int nb = 0; nb < 16; nb++) {
            mx0 = fmaxf(mx0, fmaxf(s_acc[nb][0], s_acc[nb][1]));
            mx1 = fmaxf(mx1, fmaxf(s_acc[nb][2], s_acc[nb][3]));
        }
        mx0 = fmaxf(mx0, __shfl_xor_sync(0xffffffffu, mx0, 1));
        mx0 = fmaxf(mx0, __shfl_xor_sync(0xffffffffu, mx0, 2));
        mx1 = fmaxf(mx1, __shfl_xor_sync(0xffffffffu, mx1, 1));
        mx1 = fmaxf(mx1, __shfl_xor_sync(0xffffffffu, mx1, 2));

        const float mn0 = fmaxf(m_r[0], mx0), mn1 = fmaxf(m_r[1], mx1);
        const float c0 = __expf(m_r[0] - mn0), c1 = __expf(m_r[1] - mn1);
        m_r[0] = mn0; m_r[1] = mn1;

        float sum0 = 0.f, sum1 = 0.f;
        #pragma unroll
        for (int nb = 0; nb < 16; nb++) {
            float p0 = __expf(s_acc[nb][0] - mn0);
            float p1 = __expf(s_acc[nb][1] - mn0);
            float p2 = __expf(s_acc[nb][2] - mn1);
            float p3 = __expf(s_acc[nb][3] - mn1);
            s_acc[nb][0] = p0; s_acc[nb][1] = p1;
            s_acc[nb][2] = p2; s_acc[nb][3] = p3;
            sum0 += p0 + p1; sum1 += p2 + p3;
        }
        sum0 += __shfl_xor_sync(0xffffffffu, sum0, 1);
        sum0 += __shfl_xor_sync(0xffffffffu, sum0, 2);
        sum1 += __shfl_xor_sync(0xffffffffu, sum1, 1);
        sum1 += __shfl_xor_sync(0xffffffffu, sum1, 2);
        l_r[0] = l_r[0] * c0 + sum0;
        l_r[1] = l_r[1] * c1 + sum1;

        #pragma unroll
        for (int nb = 0; nb < 8; nb++) {
            o_acc[nb][0] *= c0; o_acc[nb][1] *= c0;
            o_acc[nb][2] *= c1; o_acc[nb][3] *= c1;
        }

        // ---- O += P (Vh+Vl); P C-frags -> A-frags in registers ----
        const uint32_t vB = sbase + (OKV0 + buf * PBUF + 4608) * 4;
        #pragma unroll
        for (int kk = 0; kk < 8; kk++) {
            uint32_t pa[4];
            pa[0] = packh2(s_acc[2*kk][0],   s_acc[2*kk][1]);
            pa[1] = packh2(s_acc[2*kk][2],   s_acc[2*kk][3]);
            pa[2] = packh2(s_acc[2*kk+1][0], s_acc[2*kk+1][1]);
            pa[3] = packh2(s_acc[2*kk+1][2], s_acc[2*kk+1][3]);
            #pragma unroll
            for (int dp = 0; dp < 4; dp++) {
                uint32_t vh[4], vl[4];
                const uint32_t vad = vB + vb_off + (kk * 16 * 36 + dp * 8) * 4;
                LDSM4T(vh[0], vh[1], vh[2], vh[3], vad);
                LDSM4T(vl[0], vl[1], vl[2], vl[3], vad + 4608 * 4);
                MMA16(o_acc[2*dp],   pa, vh[0], vh[1]);
                MMA16(o_acc[2*dp],   pa, vl[0], vl[1]);
                MMA16(o_acc[2*dp+1], pa, vh[2], vh[3]);
                MMA16(o_acc[2*dp+1], pa, vl[2], vl[3]);
            }
        }
    }

    // ---- epilogue: normalize, write hi-only O [B,S,H,64] ----
    const int b = bhid >> 4, h = bhid & 15;
    const float inv0 = 1.0f / l_r[0], inv1 = 1.0f / l_r[1];
    const int qrow = q0 + wm + g;
    #pragma unroll
    for (int nb = 0; nb < 8; nb++) {
        const int col = nb * 8 + 2 * tig;
        *(__half2*)&g_Oh[(((size_t)b * S_ + qrow) * N_HEADS + h) * D_K + col] =
            __floats2half2_rn(o_acc[nb][0] * inv0, o_acc[nb][1] * inv0);
        *(__half2*)&g_Oh[(((size_t)b * S_ + qrow + 8) * N_HEADS + h) * D_K + col] =
            __floats2half2_rn(o_acc[nb][2] * inv1, o_acc[nb][3] * inv1);
    }
}

// ---------------------------------------------------------------------------
extern "C" void kernel_launch(void* const* d_in, const int* in_sizes, int n_in,
                              void* d_out, int out_size)
{
    const float* x  = (const float*)d_in[0];
    const float* Wq = (const float*)d_in[1];
    const float* bq = (const float*)d_in[2];
    const float* Wk = (const float*)d_in[3];
    const float* bk = (const float*)d_in[4];
    const float* Wv = (const float*)d_in[5];
    const float* bv = (const float*)d_in[6];
    const float* Wo = (const float*)d_in[7];
    const float* bo = (const float*)d_in[8];
    float* out = (float*)d_out;

    cudaFuncSetAttribute(gemm_f16, cudaFuncAttributeMaxDynamicSharedMemorySize,
                         GEMM_SMEM);
    cudaFuncSetAttribute(attn_f16, cudaFuncAttributeMaxDynamicSharedMemorySize,
                         ATT_SMEM);

    split_all<<<8192, 256>>>((const float4*)x, (const float4*)Wq,
                             (const float4*)Wk, (const float4*)Wv,
                             (const float4*)Wo);

    gemm_f16<<<dim3(24, M_TOT / 128), 256, GEMM_SMEM>>>(bq, bk, bv, nullptr, 0);

    attn_f16<<<dim3(S_ / 128, BH_), 256, ATT_SMEM>>>();

    gemm_f16<<<dim3(8, M_TOT / 128), 256, GEMM_SMEM>>>(bo, nullptr, nullptr, out, 1);
}

// round 13
// speedup vs baseline: 5.3998x; 1.2262x over previous
#include <cuda_runtime.h>
#include <cuda_fp16.h>
#include <cstdint>

#define D_MODEL 1024
#define N_HEADS 16
#define D_K     64
#define B_      2
#define S_      2048
#define M_TOT   (B_ * S_)
#define BH_     (B_ * N_HEADS)

// ---------------------------------------------------------------------------
// Scratch: x hi-only; W hi+lo; Q/K/V/O hi-only.
// ---------------------------------------------------------------------------
__device__ __half g_xh[(size_t)M_TOT * D_MODEL];
__device__ __half g_Wh[4][(size_t)D_MODEL * D_MODEL];
__device__ __half g_Wl[4][(size_t)D_MODEL * D_MODEL];
__device__ __half g_Qh[(size_t)BH_ * S_ * D_K];
__device__ __half g_Kh[(size_t)BH_ * S_ * D_K];
__device__ __half g_Vh[(size_t)BH_ * S_ * D_K];
__device__ __half g_Oh[(size_t)BH_ * S_ * D_K];

__device__ __forceinline__ uint32_t smem_u32(const void* p) {
    uint32_t a;
    asm("{ .reg .u64 t; cvta.to.shared.u64 t, %1; cvt.u32.u64 %0, t; }"
        : "=r"(a) : "l"(p));
    return a;
}

#define MMA16(d, a, b0, b1)                                                  \
    asm volatile(                                                            \
        "mma.sync.aligned.m16n8k16.row.col.f32.f16.f16.f32 "                 \
        "{%0,%1,%2,%3}, {%4,%5,%6,%7}, {%8,%9}, {%0,%1,%2,%3};"              \
        : "+f"((d)[0]), "+f"((d)[1]), "+f"((d)[2]), "+f"((d)[3])             \
        : "r"((a)[0]), "r"((a)[1]), "r"((a)[2]), "r"((a)[3]),                \
          "r"(b0), "r"(b1))

#define LDSM4(r0, r1, r2, r3, a)                                             \
    asm volatile("ldmatrix.sync.aligned.m8n8.x4.shared.b16 {%0,%1,%2,%3}, [%4];" \
        : "=r"(r0), "=r"(r1), "=r"(r2), "=r"(r3) : "r"(a))
#define LDSM4T(r0, r1, r2, r3, a)                                            \
    asm volatile("ldmatrix.sync.aligned.m8n8.x4.trans.shared.b16 {%0,%1,%2,%3}, [%4];" \
        : "=r"(r0), "=r"(r1), "=r"(r2), "=r"(r3) : "r"(a))

#define CPA16(saddr, gptr)                                                   \
    asm volatile("cp.async.ca.shared.global [%0], [%1], 16;"                 \
                 :: "r"(saddr), "l"(gptr))
#define CPA_COMMIT() asm volatile("cp.async.commit_group;" ::: "memory")
#define CPA_WAIT0()  asm volatile("cp.async.wait_group 0;" ::: "memory")

__device__ __forceinline__ uint32_t packh2(float a, float b) {
    __half2 h = __floats2half2_rn(a, b);
    return *(uint32_t*)&h;
}

// ---------------------------------------------------------------------------
// Split: x -> hi only; W -> hi+lo. Grid 8192: [0,4096)=x, rest W[(b-4096)>>10].
// ---------------------------------------------------------------------------
__global__ void __launch_bounds__(256) split_all(
    const float4* __restrict__ x,  const float4* __restrict__ w0,
    const float4* __restrict__ w1, const float4* __restrict__ w2,
    const float4* __restrict__ w3)
{
    const int bi = blockIdx.x;
    if (bi < 4096) {
        const int i = bi * 256 + threadIdx.x;
        float4 v = x[i];
        __half2* hi = (__half2*)g_xh;
        hi[i * 2]     = __floats2half2_rn(v.x, v.y);
        hi[i * 2 + 1] = __floats2half2_rn(v.z, v.w);
        return;
    }
    const int w = (bi - 4096) >> 10;
    const float4* ws[4] = {w0, w1, w2, w3};
    const int i = ((bi - 4096) & 1023) * 256 + threadIdx.x;
    float4 v = ws[w][i];
    __half2* hi = (__half2*)g_Wh[w];
    __half2* lo = (__half2*)g_Wl[w];
    __half2 h0 = __floats2half2_rn(v.x, v.y);
    __half2 h1 = __floats2half2_rn(v.z, v.w);
    float2 f0 = __half22float2(h0), f1 = __half22float2(h1);
    hi[i * 2]     = h0;
    hi[i * 2 + 1] = h1;
    lo[i * 2]     = __floats2half2_rn(v.x - f0.x, v.y - f0.y);
    lo[i * 2 + 1] = __floats2half2_rn(v.z - f1.x, v.w - f1.y);
}

// ---------------------------------------------------------------------------
// 2-term GEMM: C = Ah @ (Wh + Wl)^T + bias. BK=32, cp.async double buffer.
// Smem per buffer: Ah(0), Bh(GTILE), Bl(2*GTILE); stride 20 words.
// mode 0: fused QKV grid (24,32), hi-only fp16 outputs (Q folds x0.125).
// mode 1: out-proj grid (8,32), A = g_Oh, fp32 out.
// ---------------------------------------------------------------------------
#define GSTR  20
#define GTILE (128 * GSTR)
#define GBUF  (3 * GTILE)
#define GEMM_SMEM (2 * GBUF * 4)  // 61440 B

__global__ void __launch_bounds__(256, 2) gemm_f16(
    const float* __restrict__ b0p, const float* __restrict__ b1p,
    const float* __restrict__ b2p, float* __restrict__ outp, int mode)
{
    extern __shared__ uint32_t smv[];
    const int tid = threadIdx.x;
    const int wid = tid >> 5, lane = tid & 31;
    const int g   = lane >> 2, tig = lane & 3;
    const int wm  = (wid >> 2) * 64;
    const int wn  = (wid & 3) * 32;
    const int bx = blockIdx.x;
    const int m0 = blockIdx.y * 128;
    const int target = mode ? 3 : (bx >> 3);
    const int n0 = (mode ? bx : (bx & 7)) * 128;

    const __half* Ah = mode ? g_Oh : g_xh;
    const __half* Wh = g_Wh[target];
    const __half* Wl = g_Wl[target];
    const float* bias = mode ? b0p
                             : (target == 0 ? b0p : target == 1 ? b1p : b2p);
    __half* oh = nullptr;
    if (target == 0)      oh = g_Qh;
    else if (target == 1) oh = g_Kh;
    else if (target == 2) oh = g_Vh;
    const bool hs = (mode == 0);
    const float sc = (mode == 0 && target == 0) ? 0.125f : 1.0f;

    const uint32_t sbase = smem_u32(smv);

    // loaders: group 0 -> Ah row lt; group 1 -> Bh row lt (4 x 16B each);
    // all threads -> 2 Bl chunks (c = tid*2+i: row c>>2, j c&3).
    const int gsel = tid >> 7, lt = tid & 127;
    const __half* spAB = (gsel == 0 ? Ah + (size_t)(m0 + lt) * D_MODEL
                                    : Wh + (size_t)(n0 + lt) * D_MODEL);
    const uint32_t dAB = sbase + (uint32_t)((gsel ? GTILE : 0) + lt * GSTR) * 4;
    const int blr0 = (tid * 2) >> 2, blj0 = (tid * 2) & 3;
    const int blr1 = (tid * 2 + 1) >> 2, blj1 = (tid * 2 + 1) & 3;
    const __half* blsrc0 = Wl + (size_t)(n0 + blr0) * D_MODEL + blj0 * 8;
    const __half* blsrc1 = Wl + (size_t)(n0 + blr1) * D_MODEL + blj1 * 8;
    const uint32_t bld0 = sbase + (uint32_t)(2 * GTILE + blr0 * GSTR) * 4 + blj0 * 16;
    const uint32_t bld1 = sbase + (uint32_t)(2 * GTILE + blr1 * GSTR) * 4 + blj1 * 16;

    auto load_chunk = [&](int kc, int buf) {
        const uint32_t bo = buf * GBUF * 4;
        const __half* s0 = spAB + kc * 32;
        #pragma unroll
        for (int j = 0; j < 4; j++)
            CPA16(dAB + bo + j * 16, s0 + j * 8);
        CPA16(bld0 + bo, blsrc0 + kc * 32);
        CPA16(bld1 + bo, blsrc1 + kc * 32);
        CPA_COMMIT();
    };

    float acc[4][4][4];
    #pragma unroll
    for (int i = 0; i < 4; i++)
        #pragma unroll
        for (int j = 0; j < 4; j++)
            acc[i][j][0] = acc[i][j][1] = acc[i][j][2] = acc[i][j][3] = 0.f;

    load_chunk(0, 0);

    const uint32_t a_off = ((wm + (lane & 15)) * GSTR + ((lane >> 4) << 2)) * 4;
    const uint32_t b_off = ((wn + (lane & 7) + ((lane >> 4) << 3)) * GSTR
                            + (((lane >> 3) & 1) << 2)) * 4;

    for (int c = 0; c < 32; c++) {
        const int buf = c & 1;
        CPA_WAIT0();
        __syncthreads();
        if (c + 1 < 32) load_chunk(c + 1, buf ^ 1);

        const uint32_t Bb = sbase + buf * GBUF * 4;
        #pragma unroll
        for (int st = 0; st < 2; st++) {
            uint32_t bh[4][2], bl[4][2];
            #pragma unroll
            for (int p = 0; p < 2; p++) {
                const uint32_t ad = Bb + GTILE * 4 + b_off
                                    + (p * 16 * GSTR + st * 8) * 4;
                LDSM4(bh[2*p][0], bh[2*p][1], bh[2*p+1][0], bh[2*p+1][1], ad);
                LDSM4(bl[2*p][0], bl[2*p][1], bl[2*p+1][0], bl[2*p+1][1],
                      ad + GTILE * 4);
            }
            #pragma unroll
            for (int mb = 0; mb < 4; mb++) {
                uint32_t ah[4];
                const uint32_t ad = Bb + a_off + (mb * 16 * GSTR + st * 8) * 4;
                LDSM4(ah[0], ah[1], ah[2], ah[3], ad);
                #pragma unroll
                for (int nb = 0; nb < 4; nb++) {
                    MMA16(acc[mb][nb], ah, bh[nb][0], bh[nb][1]);
                    MMA16(acc[mb][nb], ah, bl[nb][0], bl[nb][1]);
                }
            }
        }
    }

    #pragma unroll
    for (int nb = 0; nb < 4; nb++) {
        const int col = n0 + wn + nb * 8 + 2 * tig;
        const float b0 = bias[col], b1 = bias[col + 1];
        #pragma unroll
        for (int mb = 0; mb < 4; mb++) {
            const int row0 = m0 + wm + mb * 16 + g;
            #pragma unroll
            for (int hf = 0; hf < 2; hf++) {
                const int row = row0 + hf * 8;
                const float v0 = (acc[mb][nb][hf * 2]     + b0) * sc;
                const float v1 = (acc[mb][nb][hf * 2 + 1] + b1) * sc;
                if (hs) {
                    const int h = col >> 6, d0 = col & 63;
                    const int bb = row >> 11, ss = row & (S_ - 1);
                    *(__half2*)&oh[(((size_t)bb * N_HEADS + h) * S_ + ss) * D_K + d0] =
                        __floats2half2_rn(v0, v1);
                } else {
                    *(float2*)&outp[(size_t)row * D_MODEL + col] =
                        make_float2(v0, v1);
                }
            }
        }
    }
}

// ---------------------------------------------------------------------------
// Flash attention, FA2 layout (8 warps x 16 q-rows), pure 1-term fp16:
// S = Qh·Kh, PV = Ph·Vh. cp.async double-buffered K/V (hi only).
// Smem (words): Qh 0 (4608), per buf (stride 9216): Kh +0, Vh +4608.
// Total (4608 + 2*9216)*4 = 92160 B.
// ---------------------------------------------------------------------------
#define OQH  0
#define OKV0 4608
#define PBUF 9216
#define ATT_SMEM ((OKV0 + 2 * PBUF) * 4)   // 92160 B

__global__ void __launch_bounds__(256, 1) attn_f16()
{
    extern __shared__ uint32_t smv[];
    const int tid  = threadIdx.x;
    const int wid  = tid >> 5, lane = tid & 31;
    const int g    = lane >> 2;
    const int tig  = lane & 3;
    const int wm   = wid * 16;
    const int q0 = blockIdx.x * 128;
    const int bhid = blockIdx.y;
    const size_t hb = (size_t)bhid * S_ * D_K;
    const uint32_t sbase = smem_u32(smv);

    // Q tile load (hi only): row = tid>>1, half = (tid&1)*32 halves.
    {
        const int row = tid >> 1, half = (tid & 1) * 32;
        const __half* src = g_Qh + hb + (size_t)(q0 + row) * D_K + half;
        uint32_t* dst = smv + OQH + row * 36 + half / 2;
        #pragma unroll
        for (int s2 = 0; s2 < 4; s2++)
            *(uint4*)(dst + s2 * 4) = *(const uint4*)(src + s2 * 8);
    }

    // K/V cp.async loader: group 0 -> Kh row lt, group 1 -> Vh row lt
    // (8 x 16B per 128B row).
    const int gsel = tid >> 7, lt = tid & 127;
    const __half* kvsrc = (gsel == 0 ? g_Kh : g_Vh) + hb + (size_t)lt * D_K;
    const uint32_t kvoff = (uint32_t)((gsel ? 4608 : 0) + lt * 36) * 4;

    auto load_tile = [&](int tt, int buf) {
        const uint32_t base = sbase + (OKV0 + buf * PBUF) * 4;
        const __half* s0 = kvsrc + (size_t)tt * 128 * D_K;
        #pragma unroll
        for (int j = 0; j < 8; j++)
            CPA16(base + kvoff + j * 16, s0 + j * 8);
        CPA_COMMIT();
    };

    load_tile(0, 0);
    __syncthreads();   // Q smem visible

    // Q fragments resident in registers.
    uint32_t qh[4][4];
    {
        const uint32_t qa_off = ((wm + (lane & 15)) * 36
                                 + ((lane >> 4) << 2)) * 4;
        #pragma unroll
        for (int st = 0; st < 4; st++) {
            const uint32_t ad = sbase + qa_off + (st * 8) * 4;
            LDSM4(qh[st][0], qh[st][1], qh[st][2], qh[st][3], ad);
        }
    }

    const uint32_t kb_off = (((lane & 7) + ((lane >> 4) << 3)) * 36
                             + (((lane >> 3) & 1) << 2)) * 4;
    const uint32_t vb_off = (((lane & 7) + (((lane >> 3) & 1) << 3)) * 36
                             + ((lane >> 4) << 2)) * 4;

    float m_r[2] = {-1e30f, -1e30f}, l_r[2] = {0.f, 0.f};
    float o_acc[8][4];
    #pragma unroll
    for (int nb = 0; nb < 8; nb++)
        o_acc[nb][0] = o_acc[nb][1] = o_acc[nb][2] = o_acc[nb][3] = 0.f;

    for (int t = 0; t < S_ / 128; t++) {
        const int buf = t & 1;
        CPA_WAIT0();
        __syncthreads();

        // ---- S = Qh Kh^T ----
        float s_acc[16][4];
        #pragma unroll
        for (int nb = 0; nb < 16; nb++)
            s_acc[nb][0] = s_acc[nb][1] = s_acc[nb][2] = s_acc[nb][3] = 0.f;

        const uint32_t kB = sbase + (OKV0 + buf * PBUF) * 4;
        #pragma unroll
        for (int st = 0; st < 4; st++) {
            #pragma unroll
            for (int p = 0; p < 8; p++) {
                uint32_t bh[4];
                const uint32_t ad = kB + kb_off + (p * 16 * 36 + st * 8) * 4;
                LDSM4(bh[0], bh[1], bh[2], bh[3], ad);
                MMA16(s_acc[2*p],   qh[st], bh[0], bh[1]);
                MMA16(s_acc[2*p+1], qh[st], bh[2], bh[3]);
            }
        }

        if (t + 1 < S_ / 128) load_tile(t + 1, buf ^ 1);

        // ---- warp-local online softmax (rows g and g+8) ----
        float mx0 = -1e30f, mx1 = -1e30f;
        #pragma unroll
        for (int nb = 0; nb < 16; nb++) {
            mx0 = fmaxf(mx0, fmaxf(s_acc[nb][0], s_acc[nb][1]));
            mx1 = fmaxf(mx1, fmaxf(s_acc[nb][2], s_acc[nb][3]));
        }
        mx0 = fmaxf(mx0, __shfl_xor_sync(0xffffffffu, mx0, 1));
        mx0 = fmaxf(mx0, __shfl_xor_sync(0xffffffffu, mx0, 2));
        mx1 = fmaxf(mx1, __shfl_xor_sync(0xffffffffu, mx1, 1));
        mx1 = fmaxf(mx1, __shfl_xor_sync(0xffffffffu, mx1, 2));

        const float mn0 = fmaxf(m_r[0], mx0), mn1 = fmaxf(m_r[1], mx1);
        const float c0 = __expf(m_r[0] - mn0), c1 = __expf(m_r[1] - mn1);
        m_r[0] = mn0; m_r[1] = mn1;

        float sum0 = 0.f, sum1 = 0.f;
        #pragma unroll
        for (int nb = 0; nb < 16; nb++) {
            float p0 = __expf(s_acc[nb][0] - mn0);
            float p1 = __expf(s_acc[nb][1] - mn0);
            float p2 = __expf(s_acc[nb][2] - mn1);
            float p3 = __expf(s_acc[nb][3] - mn1);
            s_acc[nb][0] = p0; s_acc[nb][1] = p1;
            s_acc[nb][2] = p2; s_acc[nb][3] = p3;
            sum0 += p0 + p1; sum1 += p2 + p3;
        }
        sum0 += __shfl_xor_sync(0xffffffffu, sum0, 1);
        sum0 += __shfl_xor_sync(0xffffffffu, sum0, 2);
        sum1 += __shfl_xor_sync(0xffffffffu, sum1, 1);
        sum1 += __shfl_xor_sync(0xffffffffu, sum1, 2);
        l_r[0] = l_r[0] * c0 + sum0;
        l_r[1] = l_r[1] * c1 + sum1;

        #pragma unroll
        for (int nb = 0; nb < 8; nb++) {
            o_acc[nb][0] *= c0; o_acc[nb][1] *= c0;
            o_acc[nb][2] *= c1; o_acc[nb][3] *= c1;
        }

        // ---- O += P Vh; P C-frags -> A-frags in registers ----
        const uint32_t vB = sbase + (OKV0 + buf * PBUF + 4608) * 4;
        #pragma unroll
        for (int kk = 0; kk < 8; kk++) {
            uint32_t pa[4];
            pa[0] = packh2(s_acc[2*kk][0],   s_acc[2*kk][1]);
            pa[1] = packh2(s_acc[2*kk][2],   s_acc[2*kk][3]);
            pa[2] = packh2(s_acc[2*kk+1][0], s_acc[2*kk+1][1]);
            pa[3] = packh2(s_acc[2*kk+1][2], s_acc[2*kk+1][3]);
            #pragma unroll
            for (int dp = 0; dp < 4; dp++) {
                uint32_t vh[4];
                const uint32_t vad = vB + vb_off + (kk * 16 * 36 + dp * 8) * 4;
                LDSM4T(vh[0], vh[1], vh[2], vh[3], vad);
                MMA16(o_acc[2*dp],   pa, vh[0], vh[1]);
                MMA16(o_acc[2*dp+1], pa, vh[2], vh[3]);
            }
        }
    }

    // ---- epilogue: normalize, write hi-only O [B,S,H,64] ----
    const int b = bhid >> 4, h = bhid & 15;
    const float inv0 = 1.0f / l_r[0], inv1 = 1.0f / l_r[1];
    const int qrow = q0 + wm + g;
    #pragma unroll
    for (int nb = 0; nb < 8; nb++) {
        const int col = nb * 8 + 2 * tig;
        *(__half2*)&g_Oh[(((size_t)b * S_ + qrow) * N_HEADS + h) * D_K + col] =
            __floats2half2_rn(o_acc[nb][0] * inv0, o_acc[nb][1] * inv0);
        *(__half2*)&g_Oh[(((size_t)b * S_ + qrow + 8) * N_HEADS + h) * D_K + col] =
            __floats2half2_rn(o_acc[nb][2] * inv1, o_acc[nb][3] * inv1);
    }
}

// ---------------------------------------------------------------------------
extern "C" void kernel_launch(void* const* d_in, const int* in_sizes, int n_in,
                              void* d_out, int out_size)
{
    const float* x  = (const float*)d_in[0];
    const float* Wq = (const float*)d_in[1];
    const float* bq = (const float*)d_in[2];
    const float* Wk = (const float*)d_in[3];
    const float* bk = (const float*)d_in[4];
    const float* Wv = (const float*)d_in[5];
    const float* bv = (const float*)d_in[6];
    const float* Wo = (const float*)d_in[7];
    const float* bo = (const float*)d_in[8];
    float* out = (float*)d_out;

    cudaFuncSetAttribute(gemm_f16, cudaFuncAttributeMaxDynamicSharedMemorySize,
                         GEMM_SMEM);
    cudaFuncSetAttribute(attn_f16, cudaFuncAttributeMaxDynamicSharedMemorySize,
                         ATT_SMEM);

    split_all<<<8192, 256>>>((const float4*)x, (const float4*)Wq,
                             (const float4*)Wk, (const float4*)Wv,
                             (const float4*)Wo);

    gemm_f16<<<dim3(24, M_TOT / 128), 256, GEMM_SMEM>>>(bq, bk, bv, nullptr, 0);

    attn_f16<<<dim3(S_ / 128, BH_), 256, ATT_SMEM>>>();

    gemm_f16<<<dim3(8, M_TOT / 128), 256, GEMM_SMEM>>>(bo, nullptr, nullptr, out, 1);
}

// round 14
// speedup vs baseline: 6.2065x; 1.1494x over previous
#include <cuda_runtime.h>
#include <cuda_fp16.h>
#include <cstdint>

#define D_MODEL 1024
#define N_HEADS 16
#define D_K     64
#define B_      2
#define S_      2048
#define M_TOT   (B_ * S_)
#define BH_     (B_ * N_HEADS)

// ---------------------------------------------------------------------------
// Scratch: everything hi-only fp16 (pure fp16 pipeline, RN quantization).
// ---------------------------------------------------------------------------
__device__ __half g_xh[(size_t)M_TOT * D_MODEL];
__device__ __half g_Wh[4][(size_t)D_MODEL * D_MODEL];
__device__ __half g_Qh[(size_t)BH_ * S_ * D_K];
__device__ __half g_Kh[(size_t)BH_ * S_ * D_K];
__device__ __half g_Vh[(size_t)BH_ * S_ * D_K];
__device__ __half g_Oh[(size_t)BH_ * S_ * D_K];

__device__ __forceinline__ uint32_t smem_u32(const void* p) {
    uint32_t a;
    asm("{ .reg .u64 t; cvta.to.shared.u64 t, %1; cvt.u32.u64 %0, t; }"
        : "=r"(a) : "l"(p));
    return a;
}

#define MMA16(d, a, b0, b1)                                                  \
    asm volatile(                                                            \
        "mma.sync.aligned.m16n8k16.row.col.f32.f16.f16.f32 "                 \
        "{%0,%1,%2,%3}, {%4,%5,%6,%7}, {%8,%9}, {%0,%1,%2,%3};"              \
        : "+f"((d)[0]), "+f"((d)[1]), "+f"((d)[2]), "+f"((d)[3])             \
        : "r"((a)[0]), "r"((a)[1]), "r"((a)[2]), "r"((a)[3]),                \
          "r"(b0), "r"(b1))

#define LDSM4(r0, r1, r2, r3, a)                                             \
    asm volatile("ldmatrix.sync.aligned.m8n8.x4.shared.b16 {%0,%1,%2,%3}, [%4];" \
        : "=r"(r0), "=r"(r1), "=r"(r2), "=r"(r3) : "r"(a))
#define LDSM4T(r0, r1, r2, r3, a)                                            \
    asm volatile("ldmatrix.sync.aligned.m8n8.x4.trans.shared.b16 {%0,%1,%2,%3}, [%4];" \
        : "=r"(r0), "=r"(r1), "=r"(r2), "=r"(r3) : "r"(a))

#define CPA16(saddr, gptr)                                                   \
    asm volatile("cp.async.ca.shared.global [%0], [%1], 16;"                 \
                 :: "r"(saddr), "l"(gptr))
#define CPA_COMMIT() asm volatile("cp.async.commit_group;" ::: "memory")
#define CPA_WAIT0()  asm volatile("cp.async.wait_group 0;" ::: "memory")

__device__ __forceinline__ uint32_t packh2(float a, float b) {
    __half2 h = __floats2half2_rn(a, b);
    return *(uint32_t*)&h;
}

// ---------------------------------------------------------------------------
// Split: fp32 -> fp16 (RN), hi only. Grid 8192: [0,4096)=x, rest W.
// ---------------------------------------------------------------------------
__global__ void __launch_bounds__(256) split_all(
    const float4* __restrict__ x,  const float4* __restrict__ w0,
    const float4* __restrict__ w1, const float4* __restrict__ w2,
    const float4* __restrict__ w3)
{
    const int bi = blockIdx.x;
    const float4* src; __half2* hi; int i;
    if (bi < 4096) {
        src = x; hi = (__half2*)g_xh;
        i = bi * 256 + threadIdx.x;
    } else {
        const int w = (bi - 4096) >> 10;
        const float4* ws[4] = {w0, w1, w2, w3};
        src = ws[w]; hi = (__half2*)g_Wh[w];
        i = ((bi - 4096) & 1023) * 256 + threadIdx.x;
    }
    float4 v = src[i];
    hi[i * 2]     = __floats2half2_rn(v.x, v.y);
    hi[i * 2 + 1] = __floats2half2_rn(v.z, v.w);
}

// ---------------------------------------------------------------------------
// Pure fp16 GEMM: C = Ah @ Wh^T + bias. BK=32, cp.async double buffer.
// Smem per buffer: Ah(0), Bh(GTILE); stride 20 words.
// mode 0: fused QKV grid (24,32), hi-only fp16 outputs (Q folds x0.125).
// mode 1: out-proj grid (8,32), A = g_Oh, fp32 out.
// ---------------------------------------------------------------------------
#define GSTR  20
#define GTILE (128 * GSTR)
#define GBUF  (2 * GTILE)
#define GEMM_SMEM (2 * GBUF * 4)  // 40960 B

__global__ void __launch_bounds__(256, 2) gemm_f16(
    const float* __restrict__ b0p, const float* __restrict__ b1p,
    const float* __restrict__ b2p, float* __restrict__ outp, int mode)
{
    extern __shared__ uint32_t smv[];
    const int tid = threadIdx.x;
    const int wid = tid >> 5, lane = tid & 31;
    const int g   = lane >> 2, tig = lane & 3;
    const int wm  = (wid >> 2) * 64;
    const int wn  = (wid & 3) * 32;
    const int bx = blockIdx.x;
    const int m0 = blockIdx.y * 128;
    const int target = mode ? 3 : (bx >> 3);
    const int n0 = (mode ? bx : (bx & 7)) * 128;

    const __half* Ah = mode ? g_Oh : g_xh;
    const __half* Wh = g_Wh[target];
    const float* bias = mode ? b0p
                             : (target == 0 ? b0p : target == 1 ? b1p : b2p);
    __half* oh = nullptr;
    if (target == 0)      oh = g_Qh;
    else if (target == 1) oh = g_Kh;
    else if (target == 2) oh = g_Vh;
    const bool hs = (mode == 0);
    const float sc = (mode == 0 && target == 0) ? 0.125f : 1.0f;

    const uint32_t sbase = smem_u32(smv);

    // loaders: group 0 -> Ah row lt; group 1 -> Bh row lt (4 x 16B each).
    const int gsel = tid >> 7, lt = tid & 127;
    const __half* sp = (gsel == 0 ? Ah + (size_t)(m0 + lt) * D_MODEL
                                  : Wh + (size_t)(n0 + lt) * D_MODEL);
    const uint32_t dst = sbase + (uint32_t)((gsel ? GTILE : 0) + lt * GSTR) * 4;

    auto load_chunk = [&](int kc, int buf) {
        const uint32_t bo = buf * GBUF * 4;
        const __half* s0 = sp + kc * 32;
        #pragma unroll
        for (int j = 0; j < 4; j++)
            CPA16(dst + bo + j * 16, s0 + j * 8);
        CPA_COMMIT();
    };

    float acc[4][4][4];
    #pragma unroll
    for (int i = 0; i < 4; i++)
        #pragma unroll
        for (int j = 0; j < 4; j++)
            acc[i][j][0] = acc[i][j][1] = acc[i][j][2] = acc[i][j][3] = 0.f;

    load_chunk(0, 0);

    const uint32_t a_off = ((wm + (lane & 15)) * GSTR + ((lane >> 4) << 2)) * 4;
    const uint32_t b_off = ((wn + (lane & 7) + ((lane >> 4) << 3)) * GSTR
                            + (((lane >> 3) & 1) << 2)) * 4;

    for (int c = 0; c < 32; c++) {
        const int buf = c & 1;
        CPA_WAIT0();
        __syncthreads();
        if (c + 1 < 32) load_chunk(c + 1, buf ^ 1);

        const uint32_t Bb = sbase + buf * GBUF * 4;
        #pragma unroll
        for (int st = 0; st < 2; st++) {
            uint32_t bh[4][2];
            #pragma unroll
            for (int p = 0; p < 2; p++) {
                const uint32_t ad = Bb + GTILE * 4 + b_off
                                    + (p * 16 * GSTR + st * 8) * 4;
                LDSM4(bh[2*p][0], bh[2*p][1], bh[2*p+1][0], bh[2*p+1][1], ad);
            }
            #pragma unroll
            for (int mb = 0; mb < 4; mb++) {
                uint32_t ah[4];
                const uint32_t ad = Bb + a_off + (mb * 16 * GSTR + st * 8) * 4;
                LDSM4(ah[0], ah[1], ah[2], ah[3], ad);
                #pragma unroll
                for (int nb = 0; nb < 4; nb++)
                    MMA16(acc[mb][nb], ah, bh[nb][0], bh[nb][1]);
            }
        }
    }

    #pragma unroll
    for (int nb = 0; nb < 4; nb++) {
        const int col = n0 + wn + nb * 8 + 2 * tig;
        const float b0 = bias[col], b1 = bias[col + 1];
        #pragma unroll
        for (int mb = 0; mb < 4; mb++) {
            const int row0 = m0 + wm + mb * 16 + g;
            #pragma unroll
            for (int hf = 0; hf < 2; hf++) {
                const int row = row0 + hf * 8;
                const float v0 = (acc[mb][nb][hf * 2]     + b0) * sc;
                const float v1 = (acc[mb][nb][hf * 2 + 1] + b1) * sc;
                if (hs) {
                    const int h = col >> 6, d0 = col & 63;
                    const int bb = row >> 11, ss = row & (S_ - 1);
                    *(__half2*)&oh[(((size_t)bb * N_HEADS + h) * S_ + ss) * D_K + d0] =
                        __floats2half2_rn(v0, v1);
                } else {
                    *(float2*)&outp[(size_t)row * D_MODEL + col] =
                        make_float2(v0, v1);
                }
            }
        }
    }
}

// ---------------------------------------------------------------------------
// Flash attention, FA2 layout (8 warps x 16 q-rows), pure 1-term fp16:
// S = Qh·Kh, PV = Ph·Vh. cp.async double-buffered K/V.
// Smem (words): Qh 0 (4608), per buf (stride 9216): Kh +0, Vh +4608.
// ---------------------------------------------------------------------------
#define OQH  0
#define OKV0 4608
#define PBUF 9216
#define ATT_SMEM ((OKV0 + 2 * PBUF) * 4)   // 92160 B

__global__ void __launch_bounds__(256, 1) attn_f16()
{
    extern __shared__ uint32_t smv[];
    const int tid  = threadIdx.x;
    const int wid  = tid >> 5, lane = tid & 31;
    const int g    = lane >> 2;
    const int tig  = lane & 3;
    const int wm   = wid * 16;
    const int q0 = blockIdx.x * 128;
    const int bhid = blockIdx.y;
    const size_t hb = (size_t)bhid * S_ * D_K;
    const uint32_t sbase = smem_u32(smv);

    // Q tile load: row = tid>>1, half = (tid&1)*32 halves.
    {
        const int row = tid >> 1, half = (tid & 1) * 32;
        const __half* src = g_Qh + hb + (size_t)(q0 + row) * D_K + half;
        uint32_t* dst = smv + OQH + row * 36 + half / 2;
        #pragma unroll
        for (int s2 = 0; s2 < 4; s2++)
            *(uint4*)(dst + s2 * 4) = *(const uint4*)(src + s2 * 8);
    }

    // K/V cp.async loader: group 0 -> Kh row lt, group 1 -> Vh row lt.
    const int gsel = tid >> 7, lt = tid & 127;
    const __half* kvsrc = (gsel == 0 ? g_Kh : g_Vh) + hb + (size_t)lt * D_K;
    const uint32_t kvoff = (uint32_t)((gsel ? 4608 : 0) + lt * 36) * 4;

    auto load_tile = [&](int tt, int buf) {
        const uint32_t base = sbase + (OKV0 + buf * PBUF) * 4;
        const __half* s0 = kvsrc + (size_t)tt * 128 * D_K;
        #pragma unroll
        for (int j = 0; j < 8; j++)
            CPA16(base + kvoff + j * 16, s0 + j * 8);
        CPA_COMMIT();
    };

    load_tile(0, 0);
    __syncthreads();   // Q smem visible

    // Q fragments resident in registers.
    uint32_t qh[4][4];
    {
        const uint32_t qa_off = ((wm + (lane & 15)) * 36
                                 + ((lane >> 4) << 2)) * 4;
        #pragma unroll
        for (int st = 0; st < 4; st++) {
            const uint32_t ad = sbase + qa_off + (st * 8) * 4;
            LDSM4(qh[st][0], qh[st][1], qh[st][2], qh[st][3], ad);
        }
    }

    const uint32_t kb_off = (((lane & 7) + ((lane >> 4) << 3)) * 36
                             + (((lane >> 3) & 1) << 2)) * 4;
    const uint32_t vb_off = (((lane & 7) + (((lane >> 3) & 1) << 3)) * 36
                             + ((lane >> 4) << 2)) * 4;

    float m_r[2] = {-1e30f, -1e30f}, l_r[2] = {0.f, 0.f};
    float o_acc[8][4];
    #pragma unroll
    for (int nb = 0; nb < 8; nb++)
        o_acc[nb][0] = o_acc[nb][1] = o_acc[nb][2] = o_acc[nb][3] = 0.f;

    for (int t = 0; t < S_ / 128; t++) {
        const int buf = t & 1;
        CPA_WAIT0();
        __syncthreads();

        // ---- S = Qh Kh^T ----
        float s_acc[16][4];
        #pragma unroll
        for (int nb = 0; nb < 16; nb++)
            s_acc[nb][0] = s_acc[nb][1] = s_acc[nb][2] = s_acc[nb][3] = 0.f;

        const uint32_t kB = sbase + (OKV0 + buf * PBUF) * 4;
        #pragma unroll
        for (int st = 0; st < 4; st++) {
            #pragma unroll
            for (int p = 0; p < 8; p++) {
                uint32_t bh[4];
                const uint32_t ad = kB + kb_off + (p * 16 * 36 + st * 8) * 4;
                LDSM4(bh[0], bh[1], bh[2], bh[3], ad);
                MMA16(s_acc[2*p],   qh[st], bh[0], bh[1]);
                MMA16(s_acc[2*p+1], qh[st], bh[2], bh[3]);
            }
        }

        if (t + 1 < S_ / 128) load_tile(t + 1, buf ^ 1);

        // ---- warp-local online softmax (rows g and g+8) ----
        float mx0 = -1e30f, mx1 = -1e30f;
        #pragma unroll
        for (int nb = 0; nb < 16; nb++) {
            mx0 = fmaxf(mx0, fmaxf(s_acc[nb][0], s_acc[nb][1]));
            mx1 = fmaxf(mx1, fmaxf(s_acc[nb][2], s_acc[nb][3]));
        }
        mx0 = fmaxf(mx0, __shfl_xor_sync(0xffffffffu, mx0, 1));
        mx0 = fmaxf(mx0, __shfl_xor_sync(0xffffffffu, mx0, 2));
        mx1 = fmaxf(mx1, __shfl_xor_sync(0xffffffffu, mx1, 1));
        mx1 = fmaxf(mx1, __shfl_xor_sync(0xffffffffu, mx1, 2));

        const float mn0 = fmaxf(m_r[0], mx0), mn1 = fmaxf(m_r[1], mx1);
        const float c0 = __expf(m_r[0] - mn0), c1 = __expf(m_r[1] - mn1);
        m_r[0] = mn0; m_r[1] = mn1;

        float sum0 = 0.f, sum1 = 0.f;
        #pragma unroll
        for (int nb = 0; nb < 16; nb++) {
            float p0 = __expf(s_acc[nb][0] - mn0);
            float p1 = __expf(s_acc[nb][1] - mn0);
            float p2 = __expf(s_acc[nb][2] - mn1);
            float p3 = __expf(s_acc[nb][3] - mn1);
            s_acc[nb][0] = p0; s_acc[nb][1] = p1;
            s_acc[nb][2] = p2; s_acc[nb][3] = p3;
            sum0 += p0 + p1; sum1 += p2 + p3;
        }
        sum0 += __shfl_xor_sync(0xffffffffu, sum0, 1);
        sum0 += __shfl_xor_sync(0xffffffffu, sum0, 2);
        sum1 += __shfl_xor_sync(0xffffffffu, sum1, 1);
        sum1 += __shfl_xor_sync(0xffffffffu, sum1, 2);
        l_r[0] = l_r[0] * c0 + sum0;
        l_r[1] = l_r[1] * c1 + sum1;

        #pragma unroll
        for (int nb = 0; nb < 8; nb++) {
            o_acc[nb][0] *= c0; o_acc[nb][1] *= c0;
            o_acc[nb][2] *= c1; o_acc[nb][3] *= c1;
        }

        // ---- O += P Vh; P C-frags -> A-frags in registers ----
        const uint32_t vB = sbase + (OKV0 + buf * PBUF + 4608) * 4;
        #pragma unroll
        for (int kk = 0; kk < 8; kk++) {
            uint32_t pa[4];
            pa[0] = packh2(s_acc[2*kk][0],   s_acc[2*kk][1]);
            pa[1] = packh2(s_acc[2*kk][2],   s_acc[2*kk][3]);
            pa[2] = packh2(s_acc[2*kk+1][0], s_acc[2*kk+1][1]);
            pa[3] = packh2(s_acc[2*kk+1][2], s_acc[2*kk+1][3]);
            #pragma unroll
            for (int dp = 0; dp < 4; dp++) {
                uint32_t vh[4];
                const uint32_t vad = vB + vb_off + (kk * 16 * 36 + dp * 8) * 4;
                LDSM4T(vh[0], vh[1], vh[2], vh[3], vad);
                MMA16(o_acc[2*dp],   pa, vh[0], vh[1]);
                MMA16(o_acc[2*dp+1], pa, vh[2], vh[3]);
            }
        }
    }

    // ---- epilogue: normalize, write hi-only O [B,S,H,64] ----
    const int b = bhid >> 4, h = bhid & 15;
    const float inv0 = 1.0f / l_r[0], inv1 = 1.0f / l_r[1];
    const int qrow = q0 + wm + g;
    #pragma unroll
    for (int nb = 0; nb < 8; nb++) {
        const int col = nb * 8 + 2 * tig;
        *(__half2*)&g_Oh[(((size_t)b * S_ + qrow) * N_HEADS + h) * D_K + col] =
            __floats2half2_rn(o_acc[nb][0] * inv0, o_acc[nb][1] * inv0);
        *(__half2*)&g_Oh[(((size_t)b * S_ + qrow + 8) * N_HEADS + h) * D_K + col] =
            __floats2half2_rn(o_acc[nb][2] * inv1, o_acc[nb][3] * inv1);
    }
}

// ---------------------------------------------------------------------------
extern "C" void kernel_launch(void* const* d_in, const int* in_sizes, int n_in,
                              void* d_out, int out_size)
{
    const float* x  = (const float*)d_in[0];
    const float* Wq = (const float*)d_in[1];
    const float* bq = (const float*)d_in[2];
    const float* Wk = (const float*)d_in[3];
    const float* bk = (const float*)d_in[4];
    const float* Wv = (const float*)d_in[5];
    const float* bv = (const float*)d_in[6];
    const float* Wo = (const float*)d_in[7];
    const float* bo = (const float*)d_in[8];
    float* out = (float*)d_out;

    cudaFuncSetAttribute(gemm_f16, cudaFuncAttributeMaxDynamicSharedMemorySize,
                         GEMM_SMEM);
    cudaFuncSetAttribute(attn_f16, cudaFuncAttributeMaxDynamicSharedMemorySize,
                         ATT_SMEM);

    split_all<<<8192, 256>>>((const float4*)x, (const float4*)Wq,
                             (const float4*)Wk, (const float4*)Wv,
                             (const float4*)Wo);

    gemm_f16<<<dim3(24, M_TOT / 128), 256, GEMM_SMEM>>>(bq, bk, bv, nullptr, 0);

    attn_f16<<<dim3(S_ / 128, BH_), 256, ATT_SMEM>>>();

    gemm_f16<<<dim3(8, M_TOT / 128), 256, GEMM_SMEM>>>(bo, nullptr, nullptr, out, 1);
}